// round 2
// baseline (speedup 1.0000x reference)
#include <cuda_runtime.h>
#include <math.h>
#include <stdint.h>

#define NB 8
#define NPTS 16384
#define NS 1024
#define FC 64
#define INC 91
#define PC 256
#define XSTR 92
#define R2 0.0625f

__global__ __launch_bounds__(256, 3)
void lpe_kernel(const float* __restrict__ xyz, const float* __restrict__ feat,
                const float* __restrict__ center,
                const float* __restrict__ W1, const float* __restrict__ b1,
                const float* __restrict__ g1, const float* __restrict__ be1,
                const float* __restrict__ W2, const float* __restrict__ b2,
                const float* __restrict__ g2, const float* __restrict__ be2,
                float* __restrict__ out)
{
    __shared__ float Xs[32 * XSTR];       // grouped input, 32 x 91 (stride 92)
    __shared__ float Hs[32 * PC];         // hidden activations, 32 x 256
    __shared__ float mu_s[32], rs_s[32];
    __shared__ int   sc_idx[8][32];
    __shared__ int   sc_cnt[8];
    __shared__ int   gidx[32];

    const int bs   = blockIdx.x;          // b * NS + s
    const int b    = bs >> 10;
    const int tid  = threadIdx.x;
    const int wid  = tid >> 5;
    const int lane = tid & 31;

    const float cx = center[bs * 3 + 0];
    const float cy = center[bs * 3 + 1];
    const float cz = center[bs * 3 + 2];
    const float cs = __fadd_rn(__fadd_rn(__fmul_rn(cx, cx), __fmul_rn(cy, cy)),
                               __fmul_rn(cz, cz));

    // ---- Phase 1: ball query. Each warp scans a 2048-point segment in index
    // order, compacting hits via ballot; first-32 semantics preserved. ----
    {
        const float* xb = xyz + (size_t)b * NPTS * 3;
        int cnt = 0;
        const int base = wid * 2048;
        for (int it = 0; it < 64; ++it) {
            const int n = base + it * 32 + lane;
            const float px = xb[n * 3 + 0];
            const float py = xb[n * 3 + 1];
            const float pz = xb[n * 3 + 2];
            const float ps = __fadd_rn(__fadd_rn(__fmul_rn(px, px), __fmul_rn(py, py)),
                                       __fmul_rn(pz, pz));
            const float dt = __fadd_rn(__fadd_rn(__fmul_rn(cx, px), __fmul_rn(cy, py)),
                                       __fmul_rn(cz, pz));
            const float sq = __fsub_rn(__fadd_rn(cs, ps), __fmul_rn(2.0f, dt));
            const bool hit = (sq <= R2);
            const unsigned m = __ballot_sync(0xffffffffu, hit);
            const int rank = __popc(m & ((1u << lane) - 1u));
            if (hit && (cnt + rank) < 32) sc_idx[wid][cnt + rank] = n;
            cnt += __popc(m);
            if (cnt >= 32) break;
        }
        if (lane == 0) sc_cnt[wid] = cnt < 32 ? cnt : 32;
    }
    __syncthreads();

    // ---- Merge per-warp ordered lists; pad with first hit (N if empty). ----
    if (wid == 0) {
        int val = NPTS, tot = 0;
        #pragma unroll
        for (int w = 0; w < 8; ++w) {
            const int c = sc_cnt[w];
            if (lane >= tot && lane < tot + c) val = sc_idx[w][lane - tot];
            tot += c;
        }
        const int v0 = __shfl_sync(0xffffffffu, val, 0);
        if (val == NPTS) val = v0;                      // pad with first
        gidx[lane] = val < (NPTS - 1) ? val : (NPTS - 1); // JAX clamps gathers
        out[(size_t)NB * NS * PC + (size_t)bs * 32 + lane] = (float)val;
    }
    __syncthreads();

    // ---- Phase 2: gather + relative position encoding into Xs. ----
    if (tid < 96) {
        const int k = tid / 3, d = tid - k * 3;
        const int gi = gidx[k];
        const float cd = (d == 0) ? cx : ((d == 1) ? cy : cz);
        Xs[k * XSTR + 64 + d] = xyz[((size_t)b * NPTS + gi) * 3 + d] - cd;
    }
    for (int t = tid; t < 32 * 64; t += 256) {
        const int k = t >> 6, c = t & 63;
        Xs[k * XSTR + c] = feat[((size_t)b * NPTS + gidx[k]) * 64 + c];
    }
    __syncthreads();
    for (int t = tid; t < 32 * 24; t += 256) {
        const int k = t / 24, c = t - k * 24;
        const int d = c >> 3, f = c & 7;
        const float r = Xs[k * XSTR + 64 + d];
        const float a = r * (float)(1 << (f & 3));
        Xs[k * XSTR + 67 + c] = (f < 4) ? sinf(a) : cosf(a);
    }
    __syncthreads();

    // ---- Phase 3: GEMM1 (32x91 @ 91x256). Thread tid owns column tid. ----
    float acc[32];
    {
        const float bb = b1[tid];
        #pragma unroll
        for (int r = 0; r < 32; ++r) acc[r] = bb;
        const float* w1 = W1 + tid;
        #pragma unroll 2
        for (int q = 0; q < 22; ++q) {
            const int i0 = q * 4;
            const float wa = w1[(i0 + 0) * PC];
            const float wb = w1[(i0 + 1) * PC];
            const float wc = w1[(i0 + 2) * PC];
            const float wd = w1[(i0 + 3) * PC];
            #pragma unroll
            for (int r = 0; r < 32; ++r) {
                const float4 x4 = *(const float4*)&Xs[r * XSTR + i0];
                acc[r] = fmaf(x4.x, wa, acc[r]);
                acc[r] = fmaf(x4.y, wb, acc[r]);
                acc[r] = fmaf(x4.z, wc, acc[r]);
                acc[r] = fmaf(x4.w, wd, acc[r]);
            }
        }
        #pragma unroll
        for (int i0 = 88; i0 < 91; ++i0) {
            const float w = w1[i0 * PC];
            #pragma unroll
            for (int r = 0; r < 32; ++r)
                acc[r] = fmaf(Xs[r * XSTR + i0], w, acc[r]);
        }
    }

    // LayerNorm 1 statistics (two-pass, per row across 256 channels).
    #pragma unroll
    for (int r = 0; r < 32; ++r) Hs[r * PC + tid] = acc[r];
    __syncthreads();
    #pragma unroll
    for (int rr = 0; rr < 4; ++rr) {
        const int row = wid * 4 + rr;
        float s = 0.f;
        #pragma unroll
        for (int k = 0; k < 8; ++k) s += Hs[row * PC + lane + k * 32];
        #pragma unroll
        for (int o = 16; o; o >>= 1) s += __shfl_xor_sync(0xffffffffu, s, o);
        const float mu = s * (1.0f / 256.0f);
        float v = 0.f;
        #pragma unroll
        for (int k = 0; k < 8; ++k) {
            const float d = Hs[row * PC + lane + k * 32] - mu;
            v = fmaf(d, d, v);
        }
        #pragma unroll
        for (int o = 16; o; o >>= 1) v += __shfl_xor_sync(0xffffffffu, v, o);
        if (lane == 0) {
            mu_s[row] = mu;
            rs_s[row] = rsqrtf(v * (1.0f / 256.0f) + 1e-5f);
        }
    }
    __syncthreads();

    // Apply LN1 + exact GELU, write activations back to Hs.
    {
        const float gg = g1[tid], bb = be1[tid];
        #pragma unroll
        for (int r = 0; r < 32; ++r) {
            const float v = (acc[r] - mu_s[r]) * rs_s[r] * gg + bb;
            Hs[r * PC + tid] = 0.5f * v * (1.0f + erff(v * 0.70710678118654752440f));
        }
    }
    __syncthreads();

    // ---- Phase 4: GEMM2 (32x256 @ 256x256). ----
    {
        const float bb = b2[tid];
        #pragma unroll
        for (int r = 0; r < 32; ++r) acc[r] = bb;
        const float* w2 = W2 + tid;
        #pragma unroll 2
        for (int q = 0; q < 64; ++q) {
            const int i0 = q * 4;
            const float wa = w2[(i0 + 0) * PC];
            const float wb = w2[(i0 + 1) * PC];
            const float wc = w2[(i0 + 2) * PC];
            const float wd = w2[(i0 + 3) * PC];
            #pragma unroll
            for (int r = 0; r < 32; ++r) {
                const float4 h4 = *(const float4*)&Hs[r * PC + i0];
                acc[r] = fmaf(h4.x, wa, acc[r]);
                acc[r] = fmaf(h4.y, wb, acc[r]);
                acc[r] = fmaf(h4.z, wc, acc[r]);
                acc[r] = fmaf(h4.w, wd, acc[r]);
            }
        }
    }
    __syncthreads();   // all Hs reads done before overwrite

    // LayerNorm 2 statistics.
    #pragma unroll
    for (int r = 0; r < 32; ++r) Hs[r * PC + tid] = acc[r];
    __syncthreads();
    #pragma unroll
    for (int rr = 0; rr < 4; ++rr) {
        const int row = wid * 4 + rr;
        float s = 0.f;
        #pragma unroll
        for (int k = 0; k < 8; ++k) s += Hs[row * PC + lane + k * 32];
        #pragma unroll
        for (int o = 16; o; o >>= 1) s += __shfl_xor_sync(0xffffffffu, s, o);
        const float mu = s * (1.0f / 256.0f);
        float v = 0.f;
        #pragma unroll
        for (int k = 0; k < 8; ++k) {
            const float d = Hs[row * PC + lane + k * 32] - mu;
            v = fmaf(d, d, v);
        }
        #pragma unroll
        for (int o = 16; o; o >>= 1) v += __shfl_xor_sync(0xffffffffu, v, o);
        if (lane == 0) {
            mu_s[row] = mu;
            rs_s[row] = rsqrtf(v * (1.0f / 256.0f) + 1e-5f);
        }
    }
    __syncthreads();

    // Apply LN2 (no activation) + max over the 32 neighbors.
    {
        const float gg = g2[tid], bb = be2[tid];
        float mx = -3.402823466e38f;
        #pragma unroll
        for (int r = 0; r < 32; ++r) {
            const float v = (acc[r] - mu_s[r]) * rs_s[r] * gg + bb;
            mx = fmaxf(mx, v);
        }
        out[(size_t)bs * PC + tid] = mx;
    }
}

extern "C" void kernel_launch(void* const* d_in, const int* in_sizes, int n_in,
                              void* d_out, int out_size) {
    const float* xyz    = (const float*)d_in[0];
    const float* feat   = (const float*)d_in[1];
    const float* center = (const float*)d_in[2];
    const float* W1     = (const float*)d_in[3];
    const float* b1     = (const float*)d_in[4];
    const float* g1     = (const float*)d_in[5];
    const float* be1    = (const float*)d_in[6];
    const float* W2     = (const float*)d_in[7];
    const float* b2     = (const float*)d_in[8];
    const float* g2     = (const float*)d_in[9];
    const float* be2    = (const float*)d_in[10];
    float* out = (float*)d_out;

    lpe_kernel<<<NB * NS, 256>>>(xyz, feat, center, W1, b1, g1, be1,
                                 W2, b2, g2, be2, out);
}

// round 3
// speedup vs baseline: 1.1187x; 1.1187x over previous
#include <cuda_runtime.h>
#include <math.h>
#include <stdint.h>

#define NB 8
#define NPTS 16384
#define NS 1024
#define PC 256
#define R2 0.0625f

typedef unsigned long long ull;

__device__ __forceinline__ void ffma2(ull &d, ull a, ull b) {
    asm("fma.rn.f32x2 %0, %1, %2, %0;" : "+l"(d) : "l"(a), "l"(b));
}
__device__ __forceinline__ ull pack2(float lo, float hi) {
    ull r; asm("mov.b64 %0, {%1, %2};" : "=l"(r) : "f"(lo), "f"(hi)); return r;
}
__device__ __forceinline__ float2 unpack2(ull v) {
    float2 f; asm("mov.b64 {%0, %1}, %2;" : "=f"(f.x), "=f"(f.y) : "l"(v)); return f;
}

struct Smem {
    float2 Xd[32][96];      // grouped input, duplicated {v,v}; k stride 96
    float2 Hd[32][256];     // hidden activations, duplicated
    float  pm[4][256];      // partial col-max per row-group
    float  wred[8][8];      // per-warp row reductions
    int    sc_idx[8][32];
    int    sc_cnt[8];
    int    gidx[32];
};

__global__ __launch_bounds__(256, 2)
void lpe_kernel(const float* __restrict__ xyz, const float* __restrict__ feat,
                const float* __restrict__ center,
                const float* __restrict__ W1, const float* __restrict__ b1,
                const float* __restrict__ g1, const float* __restrict__ be1,
                const float* __restrict__ W2, const float* __restrict__ b2,
                const float* __restrict__ g2, const float* __restrict__ be2,
                float* __restrict__ out)
{
    extern __shared__ char raw[];
    Smem* sm = (Smem*)raw;

    const int bs   = blockIdx.x;          // b * NS + s
    const int b    = bs >> 10;
    const int tid  = threadIdx.x;
    const int wid  = tid >> 5;
    const int lane = tid & 31;

    const float cx = center[bs * 3 + 0];
    const float cy = center[bs * 3 + 1];
    const float cz = center[bs * 3 + 2];
    const float cs = __fadd_rn(__fadd_rn(__fmul_rn(cx, cx), __fmul_rn(cy, cy)),
                               __fmul_rn(cz, cz));

    // ---- Phase 1: ball query (first-32 semantics, per-warp segments). ----
    {
        const float* xb = xyz + (size_t)b * NPTS * 3;
        int cnt = 0;
        const int base = wid * 2048;
        for (int it = 0; it < 64; ++it) {
            const int n = base + it * 32 + lane;
            const float px = xb[n * 3 + 0];
            const float py = xb[n * 3 + 1];
            const float pz = xb[n * 3 + 2];
            const float ps = __fadd_rn(__fadd_rn(__fmul_rn(px, px), __fmul_rn(py, py)),
                                       __fmul_rn(pz, pz));
            const float dt = __fadd_rn(__fadd_rn(__fmul_rn(cx, px), __fmul_rn(cy, py)),
                                       __fmul_rn(cz, pz));
            const float sq = __fsub_rn(__fadd_rn(cs, ps), __fmul_rn(2.0f, dt));
            const bool hit = (sq <= R2);
            const unsigned m = __ballot_sync(0xffffffffu, hit);
            const int rank = __popc(m & ((1u << lane) - 1u));
            if (hit && (cnt + rank) < 32) sm->sc_idx[wid][cnt + rank] = n;
            cnt += __popc(m);
            if (cnt >= 32) break;
        }
        if (lane == 0) sm->sc_cnt[wid] = cnt < 32 ? cnt : 32;
    }
    __syncthreads();

    // ---- Merge ordered per-warp lists; pad with first hit. ----
    if (wid == 0) {
        int val = NPTS, tot = 0;
        #pragma unroll
        for (int w = 0; w < 8; ++w) {
            const int c = sm->sc_cnt[w];
            if (lane >= tot && lane < tot + c) val = sm->sc_idx[w][lane - tot];
            tot += c;
        }
        const int v0 = __shfl_sync(0xffffffffu, val, 0);
        if (val == NPTS) val = v0;
        sm->gidx[lane] = val < (NPTS - 1) ? val : (NPTS - 1);
        out[(size_t)NB * NS * PC + (size_t)bs * 32 + lane] = (float)val;
    }
    __syncthreads();

    // ---- Phase 2: gather (duplicated {v,v}) + rel-pos encoding. ----
    if (tid < 96) {
        const int k = tid / 3, d = tid - k * 3;
        const int gi = sm->gidx[k];
        const float cd = (d == 0) ? cx : ((d == 1) ? cy : cz);
        const float v = xyz[((size_t)b * NPTS + gi) * 3 + d] - cd;
        sm->Xd[k][64 + d] = make_float2(v, v);
    }
    for (int t = tid; t < 32 * 64; t += 256) {
        const int k = t >> 6, c = t & 63;
        const float v = feat[((size_t)b * NPTS + sm->gidx[k]) * 64 + c];
        sm->Xd[k][c] = make_float2(v, v);
    }
    __syncthreads();
    for (int t = tid; t < 32 * 24; t += 256) {
        const int k = t / 24, c = t - k * 24;
        const int d = c >> 3, f = c & 7;
        const float r = sm->Xd[k][64 + d].x;
        const float a = r * (float)(1 << (f & 3));
        const float v = (f < 4) ? sinf(a) : cosf(a);
        sm->Xd[k][67 + c] = make_float2(v, v);
    }
    __syncthreads();

    // Thread tiling: h = row group (8 rows), cg = 4-column group.
    const int h  = tid >> 6;            // 0..3
    const int c0 = (tid & 63) * 4;      // columns c0..c0+3
    const int r0 = h * 8;               // rows r0..r0+7

    ull acc[8][2];

    // ---- Phase 3: GEMM1 (32x91 @ 91x256) with packed f32x2. ----
    {
        const float4 bb = *(const float4*)&b1[c0];
        const ull p0 = pack2(bb.x, bb.y), p1 = pack2(bb.z, bb.w);
        #pragma unroll
        for (int r = 0; r < 8; ++r) { acc[r][0] = p0; acc[r][1] = p1; }

        #pragma unroll 2
        for (int q = 0; q < 22; ++q) {
            const int i0 = q * 4;
            const ulonglong2 wA = *(const ulonglong2*)&W1[(i0 + 0) * PC + c0];
            const ulonglong2 wB = *(const ulonglong2*)&W1[(i0 + 1) * PC + c0];
            const ulonglong2 wC = *(const ulonglong2*)&W1[(i0 + 2) * PC + c0];
            const ulonglong2 wD = *(const ulonglong2*)&W1[(i0 + 3) * PC + c0];
            #pragma unroll
            for (int r = 0; r < 8; ++r) {
                const ulonglong2 xa = *(const ulonglong2*)&sm->Xd[r0 + r][i0];
                const ulonglong2 xb = *(const ulonglong2*)&sm->Xd[r0 + r][i0 + 2];
                ffma2(acc[r][0], xa.x, wA.x); ffma2(acc[r][1], xa.x, wA.y);
                ffma2(acc[r][0], xa.y, wB.x); ffma2(acc[r][1], xa.y, wB.y);
                ffma2(acc[r][0], xb.x, wC.x); ffma2(acc[r][1], xb.x, wC.y);
                ffma2(acc[r][0], xb.y, wD.x); ffma2(acc[r][1], xb.y, wD.y);
            }
        }
        #pragma unroll
        for (int kk = 88; kk < 91; ++kk) {
            const ulonglong2 w = *(const ulonglong2*)&W1[kk * PC + c0];
            #pragma unroll
            for (int r = 0; r < 8; ++r) {
                const ull x = *(const ull*)&sm->Xd[r0 + r][kk];
                ffma2(acc[r][0], x, w.x); ffma2(acc[r][1], x, w.y);
            }
        }
    }

    float mu[8], rs[8];

    // ---- LN1 statistics: register partials + warp butterfly + 2-warp merge. ----
    {
        float ps[8];
        #pragma unroll
        for (int r = 0; r < 8; ++r) {
            const float2 a = unpack2(acc[r][0]), c = unpack2(acc[r][1]);
            ps[r] = (a.x + a.y) + (c.x + c.y);
        }
        #pragma unroll
        for (int o = 16; o; o >>= 1)
            #pragma unroll
            for (int r = 0; r < 8; ++r)
                ps[r] += __shfl_xor_sync(0xffffffffu, ps[r], o);
        if (lane < 8) sm->wred[wid][lane] = ps[lane];
        __syncthreads();
        #pragma unroll
        for (int r = 0; r < 8; ++r)
            mu[r] = (sm->wred[2 * h][r] + sm->wred[2 * h + 1][r]) * (1.0f / 256.0f);
        __syncthreads();

        float vs[8];
        #pragma unroll
        for (int r = 0; r < 8; ++r) {
            const float2 a = unpack2(acc[r][0]), c = unpack2(acc[r][1]);
            const float d0 = a.x - mu[r], d1 = a.y - mu[r];
            const float d2 = c.x - mu[r], d3 = c.y - mu[r];
            vs[r] = fmaf(d0, d0, fmaf(d1, d1, fmaf(d2, d2, d3 * d3)));
        }
        #pragma unroll
        for (int o = 16; o; o >>= 1)
            #pragma unroll
            for (int r = 0; r < 8; ++r)
                vs[r] += __shfl_xor_sync(0xffffffffu, vs[r], o);
        if (lane < 8) sm->wred[wid][lane] = vs[lane];
        __syncthreads();
        #pragma unroll
        for (int r = 0; r < 8; ++r)
            rs[r] = rsqrtf((sm->wred[2 * h][r] + sm->wred[2 * h + 1][r]) * (1.0f / 256.0f)
                           + 1e-5f);
    }

    // ---- Apply LN1 + exact GELU, write duplicated activations to Hd. ----
    {
        const float4 g4 = *(const float4*)&g1[c0];
        const float4 e4 = *(const float4*)&be1[c0];
        #pragma unroll
        for (int r = 0; r < 8; ++r) {
            const float2 a = unpack2(acc[r][0]), c = unpack2(acc[r][1]);
            const float t0 = (a.x - mu[r]) * rs[r] * g4.x + e4.x;
            const float t1 = (a.y - mu[r]) * rs[r] * g4.y + e4.y;
            const float t2 = (c.x - mu[r]) * rs[r] * g4.z + e4.z;
            const float t3 = (c.y - mu[r]) * rs[r] * g4.w + e4.w;
            const float u0 = 0.5f * t0 * (1.0f + erff(t0 * 0.70710678118654752440f));
            const float u1 = 0.5f * t1 * (1.0f + erff(t1 * 0.70710678118654752440f));
            const float u2 = 0.5f * t2 * (1.0f + erff(t2 * 0.70710678118654752440f));
            const float u3 = 0.5f * t3 * (1.0f + erff(t3 * 0.70710678118654752440f));
            *(float4*)&sm->Hd[r0 + r][c0]     = make_float4(u0, u0, u1, u1);
            *(float4*)&sm->Hd[r0 + r][c0 + 2] = make_float4(u2, u2, u3, u3);
        }
    }
    __syncthreads();

    // ---- Phase 4: GEMM2 (32x256 @ 256x256) with packed f32x2. ----
    {
        const float4 bb = *(const float4*)&b2[c0];
        const ull p0 = pack2(bb.x, bb.y), p1 = pack2(bb.z, bb.w);
        #pragma unroll
        for (int r = 0; r < 8; ++r) { acc[r][0] = p0; acc[r][1] = p1; }

        #pragma unroll 2
        for (int q = 0; q < 64; ++q) {
            const int i0 = q * 4;
            const ulonglong2 wA = *(const ulonglong2*)&W2[(i0 + 0) * PC + c0];
            const ulonglong2 wB = *(const ulonglong2*)&W2[(i0 + 1) * PC + c0];
            const ulonglong2 wC = *(const ulonglong2*)&W2[(i0 + 2) * PC + c0];
            const ulonglong2 wD = *(const ulonglong2*)&W2[(i0 + 3) * PC + c0];
            #pragma unroll
            for (int r = 0; r < 8; ++r) {
                const ulonglong2 xa = *(const ulonglong2*)&sm->Hd[r0 + r][i0];
                const ulonglong2 xb = *(const ulonglong2*)&sm->Hd[r0 + r][i0 + 2];
                ffma2(acc[r][0], xa.x, wA.x); ffma2(acc[r][1], xa.x, wA.y);
                ffma2(acc[r][0], xa.y, wB.x); ffma2(acc[r][1], xa.y, wB.y);
                ffma2(acc[r][0], xb.x, wC.x); ffma2(acc[r][1], xb.x, wC.y);
                ffma2(acc[r][0], xb.y, wD.x); ffma2(acc[r][1], xb.y, wD.y);
            }
        }
    }

    // ---- LN2 statistics. ----
    {
        float ps[8];
        #pragma unroll
        for (int r = 0; r < 8; ++r) {
            const float2 a = unpack2(acc[r][0]), c = unpack2(acc[r][1]);
            ps[r] = (a.x + a.y) + (c.x + c.y);
        }
        #pragma unroll
        for (int o = 16; o; o >>= 1)
            #pragma unroll
            for (int r = 0; r < 8; ++r)
                ps[r] += __shfl_xor_sync(0xffffffffu, ps[r], o);
        __syncthreads();                 // wred free (all prior reads done)
        if (lane < 8) sm->wred[wid][lane] = ps[lane];
        __syncthreads();
        #pragma unroll
        for (int r = 0; r < 8; ++r)
            mu[r] = (sm->wred[2 * h][r] + sm->wred[2 * h + 1][r]) * (1.0f / 256.0f);
        __syncthreads();

        float vs[8];
        #pragma unroll
        for (int r = 0; r < 8; ++r) {
            const float2 a = unpack2(acc[r][0]), c = unpack2(acc[r][1]);
            const float d0 = a.x - mu[r], d1 = a.y - mu[r];
            const float d2 = c.x - mu[r], d3 = c.y - mu[r];
            vs[r] = fmaf(d0, d0, fmaf(d1, d1, fmaf(d2, d2, d3 * d3)));
        }
        #pragma unroll
        for (int o = 16; o; o >>= 1)
            #pragma unroll
            for (int r = 0; r < 8; ++r)
                vs[r] += __shfl_xor_sync(0xffffffffu, vs[r], o);
        if (lane < 8) sm->wred[wid][lane] = vs[lane];
        __syncthreads();
        #pragma unroll
        for (int r = 0; r < 8; ++r)
            rs[r] = rsqrtf((sm->wred[2 * h][r] + sm->wred[2 * h + 1][r]) * (1.0f / 256.0f)
                           + 1e-5f);
    }

    // ---- Apply LN2 + max over rows, combine across row groups. ----
    {
        const float4 g4 = *(const float4*)&g2[c0];
        const float4 e4 = *(const float4*)&be2[c0];
        float m0 = -3.402823466e38f, m1 = m0, m2 = m0, m3 = m0;
        #pragma unroll
        for (int r = 0; r < 8; ++r) {
            const float2 a = unpack2(acc[r][0]), c = unpack2(acc[r][1]);
            m0 = fmaxf(m0, (a.x - mu[r]) * rs[r] * g4.x + e4.x);
            m1 = fmaxf(m1, (a.y - mu[r]) * rs[r] * g4.y + e4.y);
            m2 = fmaxf(m2, (c.x - mu[r]) * rs[r] * g4.z + e4.z);
            m3 = fmaxf(m3, (c.y - mu[r]) * rs[r] * g4.w + e4.w);
        }
        *(float4*)&sm->pm[h][c0] = make_float4(m0, m1, m2, m3);
    }
    __syncthreads();
    {
        const float v = fmaxf(fmaxf(sm->pm[0][tid], sm->pm[1][tid]),
                              fmaxf(sm->pm[2][tid], sm->pm[3][tid]));
        out[(size_t)bs * PC + tid] = v;
    }
}

extern "C" void kernel_launch(void* const* d_in, const int* in_sizes, int n_in,
                              void* d_out, int out_size) {
    const float* xyz    = (const float*)d_in[0];
    const float* feat   = (const float*)d_in[1];
    const float* center = (const float*)d_in[2];
    const float* W1     = (const float*)d_in[3];
    const float* b1     = (const float*)d_in[4];
    const float* g1     = (const float*)d_in[5];
    const float* be1    = (const float*)d_in[6];
    const float* W2     = (const float*)d_in[7];
    const float* b2     = (const float*)d_in[8];
    const float* g2     = (const float*)d_in[9];
    const float* be2    = (const float*)d_in[10];
    float* out = (float*)d_out;

    cudaFuncSetAttribute(lpe_kernel, cudaFuncAttributeMaxDynamicSharedMemorySize,
                         (int)sizeof(Smem));
    lpe_kernel<<<NB * NS, 256, sizeof(Smem)>>>(xyz, feat, center, W1, b1, g1, be1,
                                               W2, b2, g2, be2, out);
}

// round 4
// speedup vs baseline: 1.2683x; 1.1337x over previous
#include <cuda_runtime.h>
#include <math.h>
#include <stdint.h>

#define NB 8
#define NPTS 16384
#define NS 1024
#define PC 256
#define R2 0.0625f

typedef unsigned long long ull;

__device__ __forceinline__ void ffma2(ull &d, ull a, ull b) {
    asm("fma.rn.f32x2 %0, %1, %2, %0;" : "+l"(d) : "l"(a), "l"(b));
}
__device__ __forceinline__ float2 unpack2(ull v) {
    float2 f; asm("mov.b64 {%0, %1}, %2;" : "=f"(f.x), "=f"(f.y) : "l"(v)); return f;
}

struct Smem {
    float2 Xd[32][96];      // grouped input, duplicated {v,v}
    float2 Hd[32][256];     // hidden activations, duplicated
    float  pm[4][256];      // per-warp col-max partials
    int    sc_idx[4][32];
    int    sc_cnt[4];
    int    gidx[32];
};

__global__ __launch_bounds__(128, 2)
void lpe_kernel(const float* __restrict__ xyz, const float* __restrict__ feat,
                const float* __restrict__ center,
                const float* __restrict__ W1, const float* __restrict__ b1,
                const float* __restrict__ g1, const float* __restrict__ be1,
                const float* __restrict__ W2, const float* __restrict__ b2,
                const float* __restrict__ g2, const float* __restrict__ be2,
                float* __restrict__ out)
{
    extern __shared__ char raw[];
    Smem* sm = (Smem*)raw;

    const int bs   = blockIdx.x;
    const int b    = bs >> 10;
    const int tid  = threadIdx.x;
    const int wid  = tid >> 5;
    const int lane = tid & 31;

    const float cx = center[bs * 3 + 0];
    const float cy = center[bs * 3 + 1];
    const float cz = center[bs * 3 + 2];
    const float cs = __fadd_rn(__fadd_rn(__fmul_rn(cx, cx), __fmul_rn(cy, cy)),
                               __fmul_rn(cz, cz));

    // ---- Phase 1: ball query, 4 warps x 4096-point segments, first-32 kept. ----
    {
        const float* xb = xyz + (size_t)b * NPTS * 3;
        int cnt = 0;
        const int base = wid * 4096;
        for (int it = 0; it < 128; ++it) {
            const int n = base + it * 32 + lane;
            const float px = xb[n * 3 + 0];
            const float py = xb[n * 3 + 1];
            const float pz = xb[n * 3 + 2];
            const float ps = __fadd_rn(__fadd_rn(__fmul_rn(px, px), __fmul_rn(py, py)),
                                       __fmul_rn(pz, pz));
            const float dt = __fadd_rn(__fadd_rn(__fmul_rn(cx, px), __fmul_rn(cy, py)),
                                       __fmul_rn(cz, pz));
            const float sq = __fsub_rn(__fadd_rn(cs, ps), __fmul_rn(2.0f, dt));
            const bool hit = (sq <= R2);
            const unsigned m = __ballot_sync(0xffffffffu, hit);
            const int rank = __popc(m & ((1u << lane) - 1u));
            if (hit && (cnt + rank) < 32) sm->sc_idx[wid][cnt + rank] = n;
            cnt += __popc(m);
            if (cnt >= 32) break;
        }
        if (lane == 0) sm->sc_cnt[wid] = cnt < 32 ? cnt : 32;
    }
    __syncthreads();

    if (wid == 0) {
        int val = NPTS, tot = 0;
        #pragma unroll
        for (int w = 0; w < 4; ++w) {
            const int c = sm->sc_cnt[w];
            if (lane >= tot && lane < tot + c) val = sm->sc_idx[w][lane - tot];
            tot += c;
        }
        const int v0 = __shfl_sync(0xffffffffu, val, 0);
        if (val == NPTS) val = v0;
        sm->gidx[lane] = val < (NPTS - 1) ? val : (NPTS - 1);
        out[(size_t)NB * NS * PC + (size_t)bs * 32 + lane] = (float)val;
    }
    __syncthreads();

    // ---- Phase 2: gather (duplicated) + rel-pos encoding. ----
    if (tid < 96) {
        const int k = tid / 3, d = tid - k * 3;
        const int gi = sm->gidx[k];
        const float cd = (d == 0) ? cx : ((d == 1) ? cy : cz);
        const float v = xyz[((size_t)b * NPTS + gi) * 3 + d] - cd;
        sm->Xd[k][64 + d] = make_float2(v, v);
    }
    #pragma unroll
    for (int t = tid; t < 512; t += 128) {
        const int k = t >> 4, c = (t & 15) * 4;
        const float4 v = *(const float4*)&feat[((size_t)b * NPTS + sm->gidx[k]) * 64 + c];
        sm->Xd[k][c + 0] = make_float2(v.x, v.x);
        sm->Xd[k][c + 1] = make_float2(v.y, v.y);
        sm->Xd[k][c + 2] = make_float2(v.z, v.z);
        sm->Xd[k][c + 3] = make_float2(v.w, v.w);
    }
    __syncthreads();
    #pragma unroll
    for (int t = tid; t < 768; t += 128) {
        const int k = t / 24, c = t - k * 24;
        const int d = c >> 3, f = c & 7;
        const float r = sm->Xd[k][64 + d].x;
        const float a = r * (float)(1 << (f & 3));
        const float v = (f < 4) ? sinf(a) : cosf(a);
        sm->Xd[k][67 + c] = make_float2(v, v);
    }
    __syncthreads();

    // Thread tile: warp wid owns rows r0..r0+7, lane owns cols {ca..ca+3, cb..cb+3}.
    const int r0 = wid * 8;
    const int ca = lane * 4;
    const int cb = 128 + lane * 4;

    ull acc[8][4];
    ulonglong2 A0a, A0b, A1a, A1b, B0a, B0b, B1a, B1b;

    // ---- GEMM1: 32x91 @ 91x256 with pipelined W loads. ----
    {
        const float2* Xp = &sm->Xd[0][0];
        #define LD_W(W, kk, Ta, Tb) \
            Ta = *(const ulonglong2*)&(W)[(kk) * PC + ca]; \
            Tb = *(const ulonglong2*)&(W)[(kk) * PC + cb];
        #define STEP2(Xbase, STR, kk, W0a, W0b, W1a, W1b) \
            _Pragma("unroll") \
            for (int r = 0; r < 8; ++r) { \
                const ulonglong2 x = *(const ulonglong2*)&(Xbase)[(r0 + r) * (STR) + (kk)]; \
                ffma2(acc[r][0], x.x, W0a.x); ffma2(acc[r][1], x.x, W0a.y); \
                ffma2(acc[r][2], x.x, W0b.x); ffma2(acc[r][3], x.x, W0b.y); \
                ffma2(acc[r][0], x.y, W1a.x); ffma2(acc[r][1], x.y, W1a.y); \
                ffma2(acc[r][2], x.y, W1b.x); ffma2(acc[r][3], x.y, W1b.y); \
            }

        {
            const float2 b0 = make_float2(b1[ca + 0], b1[ca + 1]);
            const float2 b1v = make_float2(b1[ca + 2], b1[ca + 3]);
            const float2 b2v = make_float2(b1[cb + 0], b1[cb + 1]);
            const float2 b3 = make_float2(b1[cb + 2], b1[cb + 3]);
            #pragma unroll
            for (int r = 0; r < 8; ++r) {
                acc[r][0] = *(const ull*)&b0;  acc[r][1] = *(const ull*)&b1v;
                acc[r][2] = *(const ull*)&b2v; acc[r][3] = *(const ull*)&b3;
            }
        }
        LD_W(W1, 0, A0a, A0b); LD_W(W1, 1, A1a, A1b);
        #pragma unroll 1
        for (int k = 0; k < 88; k += 4) {
            LD_W(W1, k + 2, B0a, B0b); LD_W(W1, k + 3, B1a, B1b);
            STEP2(Xp, 96, k, A0a, A0b, A1a, A1b);
            LD_W(W1, k + 4, A0a, A0b); LD_W(W1, k + 5, A1a, A1b);   // rows <= 89, in bounds
            STEP2(Xp, 96, k + 2, B0a, B0b, B1a, B1b);
        }
        STEP2(Xp, 96, 88, A0a, A0b, A1a, A1b);                       // k = 88, 89
        {                                                            // k = 90
            const ulonglong2 wa = *(const ulonglong2*)&W1[90 * PC + ca];
            const ulonglong2 wb = *(const ulonglong2*)&W1[90 * PC + cb];
            #pragma unroll
            for (int r = 0; r < 8; ++r) {
                const ull x = *(const ull*)&sm->Xd[r0 + r][90];
                ffma2(acc[r][0], x, wa.x); ffma2(acc[r][1], x, wa.y);
                ffma2(acc[r][2], x, wb.x); ffma2(acc[r][3], x, wb.y);
            }
        }
    }

    float mu[8], rs[8];

    // ---- LN1: warp-local (each warp covers all 256 cols of its rows). ----
    {
        float ps[8];
        #pragma unroll
        for (int r = 0; r < 8; ++r) {
            float s = 0.f;
            #pragma unroll
            for (int p = 0; p < 4; ++p) {
                const float2 a = unpack2(acc[r][p]);
                s += a.x + a.y;
            }
            ps[r] = s;
        }
        #pragma unroll
        for (int o = 16; o; o >>= 1)
            #pragma unroll
            for (int r = 0; r < 8; ++r)
                ps[r] += __shfl_xor_sync(0xffffffffu, ps[r], o);
        #pragma unroll
        for (int r = 0; r < 8; ++r) mu[r] = ps[r] * (1.0f / 256.0f);

        float vs[8];
        #pragma unroll
        for (int r = 0; r < 8; ++r) {
            float s = 0.f;
            #pragma unroll
            for (int p = 0; p < 4; ++p) {
                const float2 a = unpack2(acc[r][p]);
                const float d0 = a.x - mu[r], d1 = a.y - mu[r];
                s = fmaf(d0, d0, fmaf(d1, d1, s));
            }
            vs[r] = s;
        }
        #pragma unroll
        for (int o = 16; o; o >>= 1)
            #pragma unroll
            for (int r = 0; r < 8; ++r)
                vs[r] += __shfl_xor_sync(0xffffffffu, vs[r], o);
        #pragma unroll
        for (int r = 0; r < 8; ++r)
            rs[r] = rsqrtf(vs[r] * (1.0f / 256.0f) + 1e-5f);
    }

    // ---- Apply LN1 + exact GELU, write duplicated H. ----
    {
        const float4 ga = *(const float4*)&g1[ca];
        const float4 gb = *(const float4*)&g1[cb];
        const float4 ea = *(const float4*)&be1[ca];
        const float4 eb = *(const float4*)&be1[cb];
        #pragma unroll
        for (int r = 0; r < 8; ++r) {
            const float2 v0 = unpack2(acc[r][0]), v1 = unpack2(acc[r][1]);
            const float2 v2 = unpack2(acc[r][2]), v3 = unpack2(acc[r][3]);
            const float t0 = (v0.x - mu[r]) * rs[r] * ga.x + ea.x;
            const float t1 = (v0.y - mu[r]) * rs[r] * ga.y + ea.y;
            const float t2 = (v1.x - mu[r]) * rs[r] * ga.z + ea.z;
            const float t3 = (v1.y - mu[r]) * rs[r] * ga.w + ea.w;
            const float t4 = (v2.x - mu[r]) * rs[r] * gb.x + eb.x;
            const float t5 = (v2.y - mu[r]) * rs[r] * gb.y + eb.y;
            const float t6 = (v3.x - mu[r]) * rs[r] * gb.z + eb.z;
            const float t7 = (v3.y - mu[r]) * rs[r] * gb.w + eb.w;
            const float u0 = 0.5f * t0 * (1.0f + erff(t0 * 0.70710678118654752440f));
            const float u1 = 0.5f * t1 * (1.0f + erff(t1 * 0.70710678118654752440f));
            const float u2 = 0.5f * t2 * (1.0f + erff(t2 * 0.70710678118654752440f));
            const float u3 = 0.5f * t3 * (1.0f + erff(t3 * 0.70710678118654752440f));
            const float u4 = 0.5f * t4 * (1.0f + erff(t4 * 0.70710678118654752440f));
            const float u5 = 0.5f * t5 * (1.0f + erff(t5 * 0.70710678118654752440f));
            const float u6 = 0.5f * t6 * (1.0f + erff(t6 * 0.70710678118654752440f));
            const float u7 = 0.5f * t7 * (1.0f + erff(t7 * 0.70710678118654752440f));
            *(float4*)&sm->Hd[r0 + r][ca]     = make_float4(u0, u0, u1, u1);
            *(float4*)&sm->Hd[r0 + r][ca + 2] = make_float4(u2, u2, u3, u3);
            *(float4*)&sm->Hd[r0 + r][cb]     = make_float4(u4, u4, u5, u5);
            *(float4*)&sm->Hd[r0 + r][cb + 2] = make_float4(u6, u6, u7, u7);
        }
    }
    __syncwarp();

    // ---- GEMM2: 32x256 @ 256x256, pipelined. ----
    {
        const float2* Hp = &sm->Hd[0][0];
        {
            const float2 b0 = make_float2(b2[ca + 0], b2[ca + 1]);
            const float2 b1v = make_float2(b2[ca + 2], b2[ca + 3]);
            const float2 b2v = make_float2(b2[cb + 0], b2[cb + 1]);
            const float2 b3 = make_float2(b2[cb + 2], b2[cb + 3]);
            #pragma unroll
            for (int r = 0; r < 8; ++r) {
                acc[r][0] = *(const ull*)&b0;  acc[r][1] = *(const ull*)&b1v;
                acc[r][2] = *(const ull*)&b2v; acc[r][3] = *(const ull*)&b3;
            }
        }
        LD_W(W2, 0, A0a, A0b); LD_W(W2, 1, A1a, A1b);
        #pragma unroll 1
        for (int k = 0; k < 256; k += 4) {
            LD_W(W2, (k + 2) & 255, B0a, B0b); LD_W(W2, (k + 3) & 255, B1a, B1b);
            STEP2(Hp, 256, k, A0a, A0b, A1a, A1b);
            LD_W(W2, (k + 4) & 255, A0a, A0b); LD_W(W2, (k + 5) & 255, A1a, A1b);
            STEP2(Hp, 256, k + 2, B0a, B0b, B1a, B1b);
        }
    }

    // ---- LN2: warp-local. ----
    {
        float ps[8];
        #pragma unroll
        for (int r = 0; r < 8; ++r) {
            float s = 0.f;
            #pragma unroll
            for (int p = 0; p < 4; ++p) {
                const float2 a = unpack2(acc[r][p]);
                s += a.x + a.y;
            }
            ps[r] = s;
        }
        #pragma unroll
        for (int o = 16; o; o >>= 1)
            #pragma unroll
            for (int r = 0; r < 8; ++r)
                ps[r] += __shfl_xor_sync(0xffffffffu, ps[r], o);
        #pragma unroll
        for (int r = 0; r < 8; ++r) mu[r] = ps[r] * (1.0f / 256.0f);

        float vs[8];
        #pragma unroll
        for (int r = 0; r < 8; ++r) {
            float s = 0.f;
            #pragma unroll
            for (int p = 0; p < 4; ++p) {
                const float2 a = unpack2(acc[r][p]);
                const float d0 = a.x - mu[r], d1 = a.y - mu[r];
                s = fmaf(d0, d0, fmaf(d1, d1, s));
            }
            vs[r] = s;
        }
        #pragma unroll
        for (int o = 16; o; o >>= 1)
            #pragma unroll
            for (int r = 0; r < 8; ++r)
                vs[r] += __shfl_xor_sync(0xffffffffu, vs[r], o);
        #pragma unroll
        for (int r = 0; r < 8; ++r)
            rs[r] = rsqrtf(vs[r] * (1.0f / 256.0f) + 1e-5f);
    }

    // ---- Apply LN2 + per-warp row max. ----
    {
        const float4 ga = *(const float4*)&g2[ca];
        const float4 gb = *(const float4*)&g2[cb];
        const float4 ea = *(const float4*)&be2[ca];
        const float4 eb = *(const float4*)&be2[cb];
        float m0 = -3.402823466e38f, m1 = m0, m2 = m0, m3 = m0;
        float m4 = m0, m5 = m0, m6 = m0, m7 = m0;
        #pragma unroll
        for (int r = 0; r < 8; ++r) {
            const float2 v0 = unpack2(acc[r][0]), v1 = unpack2(acc[r][1]);
            const float2 v2 = unpack2(acc[r][2]), v3 = unpack2(acc[r][3]);
            m0 = fmaxf(m0, (v0.x - mu[r]) * rs[r] * ga.x + ea.x);
            m1 = fmaxf(m1, (v0.y - mu[r]) * rs[r] * ga.y + ea.y);
            m2 = fmaxf(m2, (v1.x - mu[r]) * rs[r] * ga.z + ea.z);
            m3 = fmaxf(m3, (v1.y - mu[r]) * rs[r] * ga.w + ea.w);
            m4 = fmaxf(m4, (v2.x - mu[r]) * rs[r] * gb.x + eb.x);
            m5 = fmaxf(m5, (v2.y - mu[r]) * rs[r] * gb.y + eb.y);
            m6 = fmaxf(m6, (v3.x - mu[r]) * rs[r] * gb.z + eb.z);
            m7 = fmaxf(m7, (v3.y - mu[r]) * rs[r] * gb.w + eb.w);
        }
        *(float4*)&sm->pm[wid][ca] = make_float4(m0, m1, m2, m3);
        *(float4*)&sm->pm[wid][cb] = make_float4(m4, m5, m6, m7);
    }
    __syncthreads();
    {
        #pragma unroll
        for (int c = tid; c < 256; c += 128) {
            const float v = fmaxf(fmaxf(sm->pm[0][c], sm->pm[1][c]),
                                  fmaxf(sm->pm[2][c], sm->pm[3][c]));
            out[(size_t)bs * PC + c] = v;
        }
    }
}

extern "C" void kernel_launch(void* const* d_in, const int* in_sizes, int n_in,
                              void* d_out, int out_size) {
    const float* xyz    = (const float*)d_in[0];
    const float* feat   = (const float*)d_in[1];
    const float* center = (const float*)d_in[2];
    const float* W1     = (const float*)d_in[3];
    const float* b1     = (const float*)d_in[4];
    const float* g1     = (const float*)d_in[5];
    const float* be1    = (const float*)d_in[6];
    const float* W2     = (const float*)d_in[7];
    const float* b2     = (const float*)d_in[8];
    const float* g2     = (const float*)d_in[9];
    const float* be2    = (const float*)d_in[10];
    float* out = (float*)d_out;

    cudaFuncSetAttribute(lpe_kernel, cudaFuncAttributeMaxDynamicSharedMemorySize,
                         (int)sizeof(Smem));
    lpe_kernel<<<NB * NS, 128, sizeof(Smem)>>>(xyz, feat, center, W1, b1, g1, be1,
                                               W2, b2, g2, be2, out);
}

// round 5
// speedup vs baseline: 1.4345x; 1.1311x over previous
#include <cuda_runtime.h>
#include <math.h>
#include <stdint.h>

#define NB 8
#define NPTS 16384
#define NS 1024
#define PC 256
#define R2 0.0625f

typedef unsigned long long ull;

__device__ __forceinline__ void ffma2(ull &d, ull a, ull b) {
    asm("fma.rn.f32x2 %0, %1, %2, %0;" : "+l"(d) : "l"(a), "l"(b));
}
__device__ __forceinline__ float2 unpack2(ull v) {
    float2 f; asm("mov.b64 {%0, %1}, %2;" : "=f"(f.x), "=f"(f.y) : "l"(v)); return f;
}

// Hd (32x256 float2, stride 256) overlays Xd (32x96 float2, stride 96) at
// offset 0 — Xd is dead after GEMM1; the overwrite is fenced by barriers.
struct Smem {
    float2 HX[32 * 256];    // 64 KB union region
    float  pm[4][256];      // per-warp col-max partials
    int    sc_idx[4][32];
    int    sc_cnt[4];
    int    gidx[32];
};

__global__ __launch_bounds__(128, 3)
void lpe_kernel(const float* __restrict__ xyz, const float* __restrict__ feat,
                const float* __restrict__ center,
                const float* __restrict__ W1, const float* __restrict__ b1,
                const float* __restrict__ g1, const float* __restrict__ be1,
                const float* __restrict__ W2, const float* __restrict__ b2,
                const float* __restrict__ g2, const float* __restrict__ be2,
                float* __restrict__ out)
{
    extern __shared__ char raw[];
    Smem* sm = (Smem*)raw;
    float2* Xd = sm->HX;    // view: [k * 96 + c]
    float2* Hd = sm->HX;    // view: [k * 256 + c]

    const int bs   = blockIdx.x;
    const int b    = bs >> 10;
    const int tid  = threadIdx.x;
    const int wid  = tid >> 5;
    const int lane = tid & 31;

    const float cx = center[bs * 3 + 0];
    const float cy = center[bs * 3 + 1];
    const float cz = center[bs * 3 + 2];
    const float cs = __fadd_rn(__fadd_rn(__fmul_rn(cx, cx), __fmul_rn(cy, cy)),
                               __fmul_rn(cz, cz));

    // ---- Phase 1: ball query, 4 warps x 4096-point segments, first-32 kept. ----
    {
        const float* xb = xyz + (size_t)b * NPTS * 3;
        int cnt = 0;
        const int base = wid * 4096;
        for (int it = 0; it < 128; ++it) {
            const int n = base + it * 32 + lane;
            const float px = xb[n * 3 + 0];
            const float py = xb[n * 3 + 1];
            const float pz = xb[n * 3 + 2];
            const float ps = __fadd_rn(__fadd_rn(__fmul_rn(px, px), __fmul_rn(py, py)),
                                       __fmul_rn(pz, pz));
            const float dt = __fadd_rn(__fadd_rn(__fmul_rn(cx, px), __fmul_rn(cy, py)),
                                       __fmul_rn(cz, pz));
            const float sq = __fsub_rn(__fadd_rn(cs, ps), __fmul_rn(2.0f, dt));
            const bool hit = (sq <= R2);
            const unsigned m = __ballot_sync(0xffffffffu, hit);
            const int rank = __popc(m & ((1u << lane) - 1u));
            if (hit && (cnt + rank) < 32) sm->sc_idx[wid][cnt + rank] = n;
            cnt += __popc(m);
            if (cnt >= 32) break;
        }
        if (lane == 0) sm->sc_cnt[wid] = cnt < 32 ? cnt : 32;
    }
    __syncthreads();

    if (wid == 0) {
        int val = NPTS, tot = 0;
        #pragma unroll
        for (int w = 0; w < 4; ++w) {
            const int c = sm->sc_cnt[w];
            if (lane >= tot && lane < tot + c) val = sm->sc_idx[w][lane - tot];
            tot += c;
        }
        const int v0 = __shfl_sync(0xffffffffu, val, 0);
        if (val == NPTS) val = v0;
        sm->gidx[lane] = val < (NPTS - 1) ? val : (NPTS - 1);
        out[(size_t)NB * NS * PC + (size_t)bs * 32 + lane] = (float)val;
    }
    __syncthreads();

    // ---- Phase 2: gather (duplicated) + rel-pos encoding into Xd view. ----
    if (tid < 96) {
        const int k = tid / 3, d = tid - k * 3;
        const int gi = sm->gidx[k];
        const float cd = (d == 0) ? cx : ((d == 1) ? cy : cz);
        const float v = xyz[((size_t)b * NPTS + gi) * 3 + d] - cd;
        Xd[k * 96 + 64 + d] = make_float2(v, v);
    }
    #pragma unroll
    for (int t = tid; t < 512; t += 128) {
        const int k = t >> 4, c = (t & 15) * 4;
        const float4 v = *(const float4*)&feat[((size_t)b * NPTS + sm->gidx[k]) * 64 + c];
        Xd[k * 96 + c + 0] = make_float2(v.x, v.x);
        Xd[k * 96 + c + 1] = make_float2(v.y, v.y);
        Xd[k * 96 + c + 2] = make_float2(v.z, v.z);
        Xd[k * 96 + c + 3] = make_float2(v.w, v.w);
    }
    __syncthreads();
    #pragma unroll
    for (int t = tid; t < 768; t += 128) {
        const int k = t / 24, c = t - k * 24;
        const int d = c >> 3, f = c & 7;
        const float r = Xd[k * 96 + 64 + d].x;
        const float a = r * (float)(1 << (f & 3));
        const float v = (f < 4) ? sinf(a) : cosf(a);
        Xd[k * 96 + 67 + c] = make_float2(v, v);
    }
    __syncthreads();

    // Thread tile: warp wid owns rows r0..r0+7, lane owns cols {ca..+3, cb..+3}.
    const int r0 = wid * 8;
    const int ca = lane * 4;
    const int cb = 128 + lane * 4;

    ull acc[8][4];
    ulonglong2 A0a, A0b, A1a, A1b, B0a, B0b, B1a, B1b;

    #define LD_W(W, kk, Ta, Tb) \
        Ta = *(const ulonglong2*)&(W)[(kk) * PC + ca]; \
        Tb = *(const ulonglong2*)&(W)[(kk) * PC + cb];
    #define STEP2(Xbase, STR, kk, W0a, W0b, W1a, W1b) \
        _Pragma("unroll") \
        for (int r = 0; r < 8; ++r) { \
            const ulonglong2 x = *(const ulonglong2*)&(Xbase)[(r0 + r) * (STR) + (kk)]; \
            ffma2(acc[r][0], x.x, W0a.x); ffma2(acc[r][1], x.x, W0a.y); \
            ffma2(acc[r][2], x.x, W0b.x); ffma2(acc[r][3], x.x, W0b.y); \
            ffma2(acc[r][0], x.y, W1a.x); ffma2(acc[r][1], x.y, W1a.y); \
            ffma2(acc[r][2], x.y, W1b.x); ffma2(acc[r][3], x.y, W1b.y); \
        }

    // ---- GEMM1: 32x91 @ 91x256 with pipelined W loads. ----
    {
        {
            const float2 b0 = make_float2(b1[ca + 0], b1[ca + 1]);
            const float2 b1v = make_float2(b1[ca + 2], b1[ca + 3]);
            const float2 b2v = make_float2(b1[cb + 0], b1[cb + 1]);
            const float2 b3 = make_float2(b1[cb + 2], b1[cb + 3]);
            #pragma unroll
            for (int r = 0; r < 8; ++r) {
                acc[r][0] = *(const ull*)&b0;  acc[r][1] = *(const ull*)&b1v;
                acc[r][2] = *(const ull*)&b2v; acc[r][3] = *(const ull*)&b3;
            }
        }
        LD_W(W1, 0, A0a, A0b); LD_W(W1, 1, A1a, A1b);
        #pragma unroll 1
        for (int k = 0; k < 88; k += 4) {
            LD_W(W1, k + 2, B0a, B0b); LD_W(W1, k + 3, B1a, B1b);
            STEP2(Xd, 96, k, A0a, A0b, A1a, A1b);
            LD_W(W1, k + 4, A0a, A0b); LD_W(W1, k + 5, A1a, A1b);   // rows <= 89, in bounds
            STEP2(Xd, 96, k + 2, B0a, B0b, B1a, B1b);
        }
        STEP2(Xd, 96, 88, A0a, A0b, A1a, A1b);                       // k = 88, 89
        {                                                            // k = 90
            const ulonglong2 wa = *(const ulonglong2*)&W1[90 * PC + ca];
            const ulonglong2 wb = *(const ulonglong2*)&W1[90 * PC + cb];
            #pragma unroll
            for (int r = 0; r < 8; ++r) {
                const ull x = *(const ull*)&Xd[(r0 + r) * 96 + 90];
                ffma2(acc[r][0], x, wa.x); ffma2(acc[r][1], x, wa.y);
                ffma2(acc[r][2], x, wb.x); ffma2(acc[r][3], x, wb.y);
            }
        }
    }

    float mu[8], rs[8];

    // ---- LN1: warp-local register reduction. ----
    {
        float ps[8];
        #pragma unroll
        for (int r = 0; r < 8; ++r) {
            float s = 0.f;
            #pragma unroll
            for (int p = 0; p < 4; ++p) {
                const float2 a = unpack2(acc[r][p]);
                s += a.x + a.y;
            }
            ps[r] = s;
        }
        #pragma unroll
        for (int o = 16; o; o >>= 1)
            #pragma unroll
            for (int r = 0; r < 8; ++r)
                ps[r] += __shfl_xor_sync(0xffffffffu, ps[r], o);
        #pragma unroll
        for (int r = 0; r < 8; ++r) mu[r] = ps[r] * (1.0f / 256.0f);

        float vs[8];
        #pragma unroll
        for (int r = 0; r < 8; ++r) {
            float s = 0.f;
            #pragma unroll
            for (int p = 0; p < 4; ++p) {
                const float2 a = unpack2(acc[r][p]);
                const float d0 = a.x - mu[r], d1 = a.y - mu[r];
                s = fmaf(d0, d0, fmaf(d1, d1, s));
            }
            vs[r] = s;
        }
        #pragma unroll
        for (int o = 16; o; o >>= 1)
            #pragma unroll
            for (int r = 0; r < 8; ++r)
                vs[r] += __shfl_xor_sync(0xffffffffu, vs[r], o);
        #pragma unroll
        for (int r = 0; r < 8; ++r)
            rs[r] = rsqrtf(vs[r] * (1.0f / 256.0f) + 1e-5f);
    }

    __syncthreads();   // all warps done reading Xd before Hd overwrite

    // ---- Apply LN1 + exact GELU, write duplicated H (over Xd). ----
    {
        const float4 ga = *(const float4*)&g1[ca];
        const float4 gb = *(const float4*)&g1[cb];
        const float4 ea = *(const float4*)&be1[ca];
        const float4 eb = *(const float4*)&be1[cb];
        #pragma unroll
        for (int r = 0; r < 8; ++r) {
            const float2 v0 = unpack2(acc[r][0]), v1 = unpack2(acc[r][1]);
            const float2 v2 = unpack2(acc[r][2]), v3 = unpack2(acc[r][3]);
            const float t0 = (v0.x - mu[r]) * rs[r] * ga.x + ea.x;
            const float t1 = (v0.y - mu[r]) * rs[r] * ga.y + ea.y;
            const float t2 = (v1.x - mu[r]) * rs[r] * ga.z + ea.z;
            const float t3 = (v1.y - mu[r]) * rs[r] * ga.w + ea.w;
            const float t4 = (v2.x - mu[r]) * rs[r] * gb.x + eb.x;
            const float t5 = (v2.y - mu[r]) * rs[r] * gb.y + eb.y;
            const float t6 = (v3.x - mu[r]) * rs[r] * gb.z + eb.z;
            const float t7 = (v3.y - mu[r]) * rs[r] * gb.w + eb.w;
            const float u0 = 0.5f * t0 * (1.0f + erff(t0 * 0.70710678118654752440f));
            const float u1 = 0.5f * t1 * (1.0f + erff(t1 * 0.70710678118654752440f));
            const float u2 = 0.5f * t2 * (1.0f + erff(t2 * 0.70710678118654752440f));
            const float u3 = 0.5f * t3 * (1.0f + erff(t3 * 0.70710678118654752440f));
            const float u4 = 0.5f * t4 * (1.0f + erff(t4 * 0.70710678118654752440f));
            const float u5 = 0.5f * t5 * (1.0f + erff(t5 * 0.70710678118654752440f));
            const float u6 = 0.5f * t6 * (1.0f + erff(t6 * 0.70710678118654752440f));
            const float u7 = 0.5f * t7 * (1.0f + erff(t7 * 0.70710678118654752440f));
            *(float4*)&Hd[(r0 + r) * 256 + ca]     = make_float4(u0, u0, u1, u1);
            *(float4*)&Hd[(r0 + r) * 256 + ca + 2] = make_float4(u2, u2, u3, u3);
            *(float4*)&Hd[(r0 + r) * 256 + cb]     = make_float4(u4, u4, u5, u5);
            *(float4*)&Hd[(r0 + r) * 256 + cb + 2] = make_float4(u6, u6, u7, u7);
        }
    }
    __syncthreads();   // Hd fully written before any warp reads it

    // ---- GEMM2: 32x256 @ 256x256, pipelined. ----
    {
        {
            const float2 b0 = make_float2(b2[ca + 0], b2[ca + 1]);
            const float2 b1v = make_float2(b2[ca + 2], b2[ca + 3]);
            const float2 b2v = make_float2(b2[cb + 0], b2[cb + 1]);
            const float2 b3 = make_float2(b2[cb + 2], b2[cb + 3]);
            #pragma unroll
            for (int r = 0; r < 8; ++r) {
                acc[r][0] = *(const ull*)&b0;  acc[r][1] = *(const ull*)&b1v;
                acc[r][2] = *(const ull*)&b2v; acc[r][3] = *(const ull*)&b3;
            }
        }
        LD_W(W2, 0, A0a, A0b); LD_W(W2, 1, A1a, A1b);
        #pragma unroll 1
        for (int k = 0; k < 256; k += 4) {
            LD_W(W2, (k + 2) & 255, B0a, B0b); LD_W(W2, (k + 3) & 255, B1a, B1b);
            STEP2(Hd, 256, k, A0a, A0b, A1a, A1b);
            LD_W(W2, (k + 4) & 255, A0a, A0b); LD_W(W2, (k + 5) & 255, A1a, A1b);
            STEP2(Hd, 256, k + 2, B0a, B0b, B1a, B1b);
        }
    }

    // ---- LN2: warp-local. ----
    {
        float ps[8];
        #pragma unroll
        for (int r = 0; r < 8; ++r) {
            float s = 0.f;
            #pragma unroll
            for (int p = 0; p < 4; ++p) {
                const float2 a = unpack2(acc[r][p]);
                s += a.x + a.y;
            }
            ps[r] = s;
        }
        #pragma unroll
        for (int o = 16; o; o >>= 1)
            #pragma unroll
            for (int r = 0; r < 8; ++r)
                ps[r] += __shfl_xor_sync(0xffffffffu, ps[r], o);
        #pragma unroll
        for (int r = 0; r < 8; ++r) mu[r] = ps[r] * (1.0f / 256.0f);

        float vs[8];
        #pragma unroll
        for (int r = 0; r < 8; ++r) {
            float s = 0.f;
            #pragma unroll
            for (int p = 0; p < 4; ++p) {
                const float2 a = unpack2(acc[r][p]);
                const float d0 = a.x - mu[r], d1 = a.y - mu[r];
                s = fmaf(d0, d0, fmaf(d1, d1, s));
            }
            vs[r] = s;
        }
        #pragma unroll
        for (int o = 16; o; o >>= 1)
            #pragma unroll
            for (int r = 0; r < 8; ++r)
                vs[r] += __shfl_xor_sync(0xffffffffu, vs[r], o);
        #pragma unroll
        for (int r = 0; r < 8; ++r)
            rs[r] = rsqrtf(vs[r] * (1.0f / 256.0f) + 1e-5f);
    }

    // ---- Apply LN2 + per-warp row max. ----
    {
        const float4 ga = *(const float4*)&g2[ca];
        const float4 gb = *(const float4*)&g2[cb];
        const float4 ea = *(const float4*)&be2[ca];
        const float4 eb = *(const float4*)&be2[cb];
        float m0 = -3.402823466e38f, m1 = m0, m2 = m0, m3 = m0;
        float m4 = m0, m5 = m0, m6 = m0, m7 = m0;
        #pragma unroll
        for (int r = 0; r < 8; ++r) {
            const float2 v0 = unpack2(acc[r][0]), v1 = unpack2(acc[r][1]);
            const float2 v2 = unpack2(acc[r][2]), v3 = unpack2(acc[r][3]);
            m0 = fmaxf(m0, (v0.x - mu[r]) * rs[r] * ga.x + ea.x);
            m1 = fmaxf(m1, (v0.y - mu[r]) * rs[r] * ga.y + ea.y);
            m2 = fmaxf(m2, (v1.x - mu[r]) * rs[r] * ga.z + ea.z);
            m3 = fmaxf(m3, (v1.y - mu[r]) * rs[r] * ga.w + ea.w);
            m4 = fmaxf(m4, (v2.x - mu[r]) * rs[r] * gb.x + eb.x);
            m5 = fmaxf(m5, (v2.y - mu[r]) * rs[r] * gb.y + eb.y);
            m6 = fmaxf(m6, (v3.x - mu[r]) * rs[r] * gb.z + eb.z);
            m7 = fmaxf(m7, (v3.y - mu[r]) * rs[r] * gb.w + eb.w);
        }
        *(float4*)&sm->pm[wid][ca] = make_float4(m0, m1, m2, m3);
        *(float4*)&sm->pm[wid][cb] = make_float4(m4, m5, m6, m7);
    }
    __syncthreads();
    {
        #pragma unroll
        for (int c = tid; c < 256; c += 128) {
            const float v = fmaxf(fmaxf(sm->pm[0][c], sm->pm[1][c]),
                                  fmaxf(sm->pm[2][c], sm->pm[3][c]));
            out[(size_t)bs * PC + c] = v;
        }
    }
}

extern "C" void kernel_launch(void* const* d_in, const int* in_sizes, int n_in,
                              void* d_out, int out_size) {
    const float* xyz    = (const float*)d_in[0];
    const float* feat   = (const float*)d_in[1];
    const float* center = (const float*)d_in[2];
    const float* W1     = (const float*)d_in[3];
    const float* b1     = (const float*)d_in[4];
    const float* g1     = (const float*)d_in[5];
    const float* be1    = (const float*)d_in[6];
    const float* W2     = (const float*)d_in[7];
    const float* b2     = (const float*)d_in[8];
    const float* g2     = (const float*)d_in[9];
    const float* be2    = (const float*)d_in[10];
    float* out = (float*)d_out;

    cudaFuncSetAttribute(lpe_kernel, cudaFuncAttributeMaxDynamicSharedMemorySize,
                         (int)sizeof(Smem));
    lpe_kernel<<<NB * NS, 128, sizeof(Smem)>>>(xyz, feat, center, W1, b1, g1, be1,
                                               W2, b2, g2, be2, out);
}

// round 6
// speedup vs baseline: 3.0201x; 2.1053x over previous
#include <cuda_runtime.h>
#include <math.h>
#include <stdint.h>

#define NB 8
#define NPTS 16384
#define NS 1024
#define PC 256
#define R2 0.0625f

// ---- precomputed W fragments (B-operand layout for mma.m16n8k16) ----
// index = (kt*32 + nt)*32 + lane ; {x,y,z,w} = {b0hi, b1hi, b0lo, b1lo}
__device__ uint4 W1frag[6 * 32 * 32];     // K padded 91 -> 96
__device__ uint4 W2frag[16 * 32 * 32];

__device__ __forceinline__ unsigned pack_bf16(float e0, float e1) {
    unsigned r;
    asm("cvt.rn.bf16x2.f32 %0, %1, %2;" : "=r"(r) : "f"(e1), "f"(e0));
    return r;   // low half = bf16(e0), high half = bf16(e1)
}
__device__ __forceinline__ void split2(float e0, float e1, unsigned &hi, unsigned &lo) {
    hi = pack_bf16(e0, e1);
    const float h0 = __uint_as_float(hi << 16);
    const float h1 = __uint_as_float(hi & 0xffff0000u);
    lo = pack_bf16(e0 - h0, e1 - h1);
}
__device__ __forceinline__ void mma16816(float* c, unsigned a0, unsigned a1,
                                         unsigned a2, unsigned a3,
                                         unsigned b0, unsigned b1) {
    asm("mma.sync.aligned.m16n8k16.row.col.f32.bf16.bf16.f32 "
        "{%0,%1,%2,%3}, {%4,%5,%6,%7}, {%8,%9}, {%0,%1,%2,%3};"
        : "+f"(c[0]), "+f"(c[1]), "+f"(c[2]), "+f"(c[3])
        : "r"(a0), "r"(a1), "r"(a2), "r"(a3), "r"(b0), "r"(b1));
}

// ---- prep: build W fragments (runs every launch; idempotent) ----
__global__ void prep_kernel(const float* __restrict__ W1, const float* __restrict__ W2) {
    const int t = blockIdx.x * blockDim.x + threadIdx.x;
    if (t < 6144) {                                   // W1: 6 kt * 32 nt * 32 lanes
        const int lane = t & 31, nt = (t >> 5) & 31, kt = t >> 10;
        const int k0 = kt * 16 + (lane & 3) * 2;
        const int n  = nt * 8 + (lane >> 2);
        const float e00 = (k0     < 91) ? W1[(k0    ) * PC + n] : 0.f;
        const float e01 = (k0 + 1 < 91) ? W1[(k0 + 1) * PC + n] : 0.f;
        const float e10 = (k0 + 8 < 91) ? W1[(k0 + 8) * PC + n] : 0.f;
        const float e11 = (k0 + 9 < 91) ? W1[(k0 + 9) * PC + n] : 0.f;
        uint4 v;
        split2(e00, e01, v.x, v.z);
        split2(e10, e11, v.y, v.w);
        W1frag[t] = v;
    } else if (t < 6144 + 16384) {                    // W2: 16 kt * 32 nt * 32 lanes
        const int u = t - 6144;
        const int lane = u & 31, nt = (u >> 5) & 31, kt = u >> 10;
        const int k0 = kt * 16 + (lane & 3) * 2;
        const int n  = nt * 8 + (lane >> 2);
        uint4 v;
        split2(W2[k0 * PC + n],       W2[(k0 + 1) * PC + n], v.x, v.z);
        split2(W2[(k0 + 8) * PC + n], W2[(k0 + 9) * PC + n], v.y, v.w);
        W2frag[u] = v;
    }
}

struct Smem {
    float Xs[32][98];               // grouped input fp32 (K padded to 96, +2 stride pad)
    uint4 Hfrag[16][2][32][2];      // [kt][mt][lane][{hi,lo}] A-fragments of H, 32 KB
    float rp1[4][32];               // cross-warp row partials
    float rp2[4][32];
    int   sc_idx[4][32];
    int   sc_cnt[4];
    int   gidx[32];
};

__global__ __launch_bounds__(128, 3)
void lpe_kernel(const float* __restrict__ xyz, const float* __restrict__ feat,
                const float* __restrict__ center,
                const float* __restrict__ b1, const float* __restrict__ g1,
                const float* __restrict__ be1,
                const float* __restrict__ b2, const float* __restrict__ g2,
                const float* __restrict__ be2,
                float* __restrict__ out)
{
    extern __shared__ char rawsm[];
    Smem* sm = (Smem*)rawsm;

    const int bs   = blockIdx.x;
    const int b    = bs >> 10;
    const int tid  = threadIdx.x;
    const int w    = tid >> 5;
    const int lane = tid & 31;
    const int g    = lane >> 2;       // 0..7
    const int tq   = lane & 3;        // 0..3

    const float cx = center[bs * 3 + 0];
    const float cy = center[bs * 3 + 1];
    const float cz = center[bs * 3 + 2];
    const float cs = __fadd_rn(__fadd_rn(__fmul_rn(cx, cx), __fmul_rn(cy, cy)),
                               __fmul_rn(cz, cz));

    // ---- Phase 1: ball query, 4 warps x 4096-point segments, first-32 kept. ----
    {
        const float* xb = xyz + (size_t)b * NPTS * 3;
        int cnt = 0;
        const int base = w * 4096;
        for (int it = 0; it < 128; ++it) {
            const int n = base + it * 32 + lane;
            const float px = xb[n * 3 + 0];
            const float py = xb[n * 3 + 1];
            const float pz = xb[n * 3 + 2];
            const float ps = __fadd_rn(__fadd_rn(__fmul_rn(px, px), __fmul_rn(py, py)),
                                       __fmul_rn(pz, pz));
            const float dt = __fadd_rn(__fadd_rn(__fmul_rn(cx, px), __fmul_rn(cy, py)),
                                       __fmul_rn(cz, pz));
            const float sq = __fsub_rn(__fadd_rn(cs, ps), __fmul_rn(2.0f, dt));
            const bool hit = (sq <= R2);
            const unsigned m = __ballot_sync(0xffffffffu, hit);
            const int rank = __popc(m & ((1u << lane) - 1u));
            if (hit && (cnt + rank) < 32) sm->sc_idx[w][cnt + rank] = n;
            cnt += __popc(m);
            if (cnt >= 32) break;
        }
        if (lane == 0) sm->sc_cnt[w] = cnt < 32 ? cnt : 32;
    }
    __syncthreads();

    if (w == 0) {
        int val = NPTS, tot = 0;
        #pragma unroll
        for (int ww = 0; ww < 4; ++ww) {
            const int c = sm->sc_cnt[ww];
            if (lane >= tot && lane < tot + c) val = sm->sc_idx[ww][lane - tot];
            tot += c;
        }
        const int v0 = __shfl_sync(0xffffffffu, val, 0);
        if (val == NPTS) val = v0;
        sm->gidx[lane] = val < (NPTS - 1) ? val : (NPTS - 1);
        out[(size_t)NB * NS * PC + (size_t)bs * 32 + lane] = (float)val;
    }
    __syncthreads();

    // ---- Phase 2: gather + rel-pos into Xs (fp32, non-duplicated). ----
    if (tid < 96) {
        const int k = tid / 3, d = tid - k * 3;
        const int gi = sm->gidx[k];
        const float cd = (d == 0) ? cx : ((d == 1) ? cy : cz);
        sm->Xs[k][64 + d] = xyz[((size_t)b * NPTS + gi) * 3 + d] - cd;
    }
    #pragma unroll
    for (int t = tid; t < 512; t += 128) {
        const int k = t >> 4, c = (t & 15) * 4;
        const float4 v = *(const float4*)&feat[((size_t)b * NPTS + sm->gidx[k]) * 64 + c];
        sm->Xs[k][c + 0] = v.x; sm->Xs[k][c + 1] = v.y;
        sm->Xs[k][c + 2] = v.z; sm->Xs[k][c + 3] = v.w;
    }
    #pragma unroll
    for (int t = tid; t < 32 * 7; t += 128) {       // zero pad cols 91..97
        sm->Xs[t / 7][91 + t % 7] = 0.f;
    }
    __syncthreads();
    #pragma unroll
    for (int t = tid; t < 768; t += 128) {
        const int k = t / 24, c = t - k * 24;
        const int d = c >> 3, f = c & 7;
        const float r = sm->Xs[k][64 + d];
        const float a = r * (float)(1 << (f & 3));
        sm->Xs[k][67 + c] = (f < 4) ? sinf(a) : cosf(a);
    }
    __syncthreads();

    float acc[2][8][4];                 // [mt][nt][c0..c3]
    const int ncol0 = w * 64 + tq * 2;  // this lane's first col within warp cols

    // ---- GEMM1: C = X(32x96) @ W1(96x256), bf16 2-way split (3 MMAs). ----
    {
        #pragma unroll
        for (int nt = 0; nt < 8; ++nt) {
            const float2 bp = *(const float2*)&b1[ncol0 + nt * 8];
            acc[0][nt][0] = bp.x; acc[0][nt][1] = bp.y;
            acc[0][nt][2] = bp.x; acc[0][nt][3] = bp.y;
            acc[1][nt][0] = bp.x; acc[1][nt][1] = bp.y;
            acc[1][nt][2] = bp.x; acc[1][nt][3] = bp.y;
        }
        #pragma unroll
        for (int kt = 0; kt < 6; ++kt) {
            unsigned Ahi[2][4], Alo[2][4];
            #pragma unroll
            for (int mt = 0; mt < 2; ++mt) {
                const int r = mt * 16 + g;
                const int k0 = kt * 16 + tq * 2;
                const float2 p0 = *(const float2*)&sm->Xs[r][k0];
                const float2 p1 = *(const float2*)&sm->Xs[r + 8][k0];
                const float2 p2 = *(const float2*)&sm->Xs[r][k0 + 8];
                const float2 p3 = *(const float2*)&sm->Xs[r + 8][k0 + 8];
                split2(p0.x, p0.y, Ahi[mt][0], Alo[mt][0]);
                split2(p1.x, p1.y, Ahi[mt][1], Alo[mt][1]);
                split2(p2.x, p2.y, Ahi[mt][2], Alo[mt][2]);
                split2(p3.x, p3.y, Ahi[mt][3], Alo[mt][3]);
            }
            #pragma unroll
            for (int nt = 0; nt < 8; ++nt) {
                const uint4 B = W1frag[(kt * 32 + w * 8 + nt) * 32 + lane];
                #pragma unroll
                for (int mt = 0; mt < 2; ++mt) {
                    mma16816(acc[mt][nt], Ahi[mt][0], Ahi[mt][1], Ahi[mt][2], Ahi[mt][3], B.x, B.y);
                    mma16816(acc[mt][nt], Ahi[mt][0], Ahi[mt][1], Ahi[mt][2], Ahi[mt][3], B.z, B.w);
                    mma16816(acc[mt][nt], Alo[mt][0], Alo[mt][1], Alo[mt][2], Alo[mt][3], B.x, B.y);
                }
            }
        }
    }

    float mu[2][2], rs[2][2];

    // ---- LN1 stats: lane partials -> shfl over t -> cross-warp smem. ----
    {
        float s[2][2];
        #pragma unroll
        for (int mt = 0; mt < 2; ++mt)
            #pragma unroll
            for (int rh = 0; rh < 2; ++rh) {
                float v = 0.f;
                #pragma unroll
                for (int nt = 0; nt < 8; ++nt)
                    v += acc[mt][nt][2 * rh] + acc[mt][nt][2 * rh + 1];
                s[mt][rh] = v;
            }
        #pragma unroll
        for (int o = 1; o <= 2; o <<= 1)
            #pragma unroll
            for (int mt = 0; mt < 2; ++mt)
                #pragma unroll
                for (int rh = 0; rh < 2; ++rh)
                    s[mt][rh] += __shfl_xor_sync(0xffffffffu, s[mt][rh], o);
        if (tq == 0)
            #pragma unroll
            for (int mt = 0; mt < 2; ++mt)
                #pragma unroll
                for (int rh = 0; rh < 2; ++rh)
                    sm->rp1[w][mt * 16 + rh * 8 + g] = s[mt][rh];
        __syncthreads();
        #pragma unroll
        for (int mt = 0; mt < 2; ++mt)
            #pragma unroll
            for (int rh = 0; rh < 2; ++rh) {
                const int row = mt * 16 + rh * 8 + g;
                mu[mt][rh] = (sm->rp1[0][row] + sm->rp1[1][row] +
                              sm->rp1[2][row] + sm->rp1[3][row]) * (1.0f / 256.0f);
            }
        float vsum[2][2];
        #pragma unroll
        for (int mt = 0; mt < 2; ++mt)
            #pragma unroll
            for (int rh = 0; rh < 2; ++rh) {
                float v = 0.f;
                #pragma unroll
                for (int nt = 0; nt < 8; ++nt) {
                    const float d0 = acc[mt][nt][2 * rh]     - mu[mt][rh];
                    const float d1 = acc[mt][nt][2 * rh + 1] - mu[mt][rh];
                    v = fmaf(d0, d0, fmaf(d1, d1, v));
                }
                vsum[mt][rh] = v;
            }
        #pragma unroll
        for (int o = 1; o <= 2; o <<= 1)
            #pragma unroll
            for (int mt = 0; mt < 2; ++mt)
                #pragma unroll
                for (int rh = 0; rh < 2; ++rh)
                    vsum[mt][rh] += __shfl_xor_sync(0xffffffffu, vsum[mt][rh], o);
        if (tq == 0)
            #pragma unroll
            for (int mt = 0; mt < 2; ++mt)
                #pragma unroll
                for (int rh = 0; rh < 2; ++rh)
                    sm->rp2[w][mt * 16 + rh * 8 + g] = vsum[mt][rh];
        __syncthreads();
        #pragma unroll
        for (int mt = 0; mt < 2; ++mt)
            #pragma unroll
            for (int rh = 0; rh < 2; ++rh) {
                const int row = mt * 16 + rh * 8 + g;
                rs[mt][rh] = rsqrtf((sm->rp2[0][row] + sm->rp2[1][row] +
                                     sm->rp2[2][row] + sm->rp2[3][row]) * (1.0f / 256.0f)
                                    + 1e-5f);
            }
    }

    // ---- LN1 apply + GELU, pack into Hfrag (A-fragment layout for GEMM2). ----
    {
        #pragma unroll
        for (int mt = 0; mt < 2; ++mt)
            #pragma unroll
            for (int j = 0; j < 4; ++j) {
                float u[2][4];
                #pragma unroll
                for (int p = 0; p < 2; ++p) {          // ntiles 2j, 2j+1
                    const int nt = 2 * j + p;
                    const float2 gp = *(const float2*)&g1[ncol0 + nt * 8];
                    const float2 ep = *(const float2*)&be1[ncol0 + nt * 8];
                    #pragma unroll
                    for (int q = 0; q < 4; ++q) {
                        const int rh = q >> 1, e = q & 1;
                        const float gg = e ? gp.y : gp.x;
                        const float ee = e ? ep.y : ep.x;
                        const float t = (acc[mt][nt][q] - mu[mt][rh]) * rs[mt][rh] * gg + ee;
                        u[p][q] = 0.5f * t * (1.0f + erff(t * 0.70710678118654752440f));
                    }
                }
                uint4 hi, lo;
                split2(u[0][0], u[0][1], hi.x, lo.x);
                split2(u[0][2], u[0][3], hi.y, lo.y);
                split2(u[1][0], u[1][1], hi.z, lo.z);
                split2(u[1][2], u[1][3], hi.w, lo.w);
                sm->Hfrag[w * 4 + j][mt][lane][0] = hi;
                sm->Hfrag[w * 4 + j][mt][lane][1] = lo;
            }
    }
    __syncthreads();

    // ---- GEMM2: C = H(32x256) @ W2(256x256), bf16 2-way split. ----
    {
        #pragma unroll
        for (int nt = 0; nt < 8; ++nt) {
            const float2 bp = *(const float2*)&b2[ncol0 + nt * 8];
            acc[0][nt][0] = bp.x; acc[0][nt][1] = bp.y;
            acc[0][nt][2] = bp.x; acc[0][nt][3] = bp.y;
            acc[1][nt][0] = bp.x; acc[1][nt][1] = bp.y;
            acc[1][nt][2] = bp.x; acc[1][nt][3] = bp.y;
        }
        #pragma unroll 2
        for (int kt = 0; kt < 16; ++kt) {
            const uint4 Ahi0 = sm->Hfrag[kt][0][lane][0];
            const uint4 Alo0 = sm->Hfrag[kt][0][lane][1];
            const uint4 Ahi1 = sm->Hfrag[kt][1][lane][0];
            const uint4 Alo1 = sm->Hfrag[kt][1][lane][1];
            #pragma unroll
            for (int nt = 0; nt < 8; ++nt) {
                const uint4 B = W2frag[(kt * 32 + w * 8 + nt) * 32 + lane];
                mma16816(acc[0][nt], Ahi0.x, Ahi0.y, Ahi0.z, Ahi0.w, B.x, B.y);
                mma16816(acc[0][nt], Ahi0.x, Ahi0.y, Ahi0.z, Ahi0.w, B.z, B.w);
                mma16816(acc[0][nt], Alo0.x, Alo0.y, Alo0.z, Alo0.w, B.x, B.y);
                mma16816(acc[1][nt], Ahi1.x, Ahi1.y, Ahi1.z, Ahi1.w, B.x, B.y);
                mma16816(acc[1][nt], Ahi1.x, Ahi1.y, Ahi1.z, Ahi1.w, B.z, B.w);
                mma16816(acc[1][nt], Alo1.x, Alo1.y, Alo1.z, Alo1.w, B.x, B.y);
            }
        }
    }

    // ---- LN2 stats (same pattern). ----
    {
        float s[2][2];
        #pragma unroll
        for (int mt = 0; mt < 2; ++mt)
            #pragma unroll
            for (int rh = 0; rh < 2; ++rh) {
                float v = 0.f;
                #pragma unroll
                for (int nt = 0; nt < 8; ++nt)
                    v += acc[mt][nt][2 * rh] + acc[mt][nt][2 * rh + 1];
                s[mt][rh] = v;
            }
        #pragma unroll
        for (int o = 1; o <= 2; o <<= 1)
            #pragma unroll
            for (int mt = 0; mt < 2; ++mt)
                #pragma unroll
                for (int rh = 0; rh < 2; ++rh)
                    s[mt][rh] += __shfl_xor_sync(0xffffffffu, s[mt][rh], o);
        if (tq == 0)
            #pragma unroll
            for (int mt = 0; mt < 2; ++mt)
                #pragma unroll
                for (int rh = 0; rh < 2; ++rh)
                    sm->rp1[w][mt * 16 + rh * 8 + g] = s[mt][rh];
        __syncthreads();
        #pragma unroll
        for (int mt = 0; mt < 2; ++mt)
            #pragma unroll
            for (int rh = 0; rh < 2; ++rh) {
                const int row = mt * 16 + rh * 8 + g;
                mu[mt][rh] = (sm->rp1[0][row] + sm->rp1[1][row] +
                              sm->rp1[2][row] + sm->rp1[3][row]) * (1.0f / 256.0f);
            }
        float vsum[2][2];
        #pragma unroll
        for (int mt = 0; mt < 2; ++mt)
            #pragma unroll
            for (int rh = 0; rh < 2; ++rh) {
                float v = 0.f;
                #pragma unroll
                for (int nt = 0; nt < 8; ++nt) {
                    const float d0 = acc[mt][nt][2 * rh]     - mu[mt][rh];
                    const float d1 = acc[mt][nt][2 * rh + 1] - mu[mt][rh];
                    v = fmaf(d0, d0, fmaf(d1, d1, v));
                }
                vsum[mt][rh] = v;
            }
        #pragma unroll
        for (int o = 1; o <= 2; o <<= 1)
            #pragma unroll
            for (int mt = 0; mt < 2; ++mt)
                #pragma unroll
                for (int rh = 0; rh < 2; ++rh)
                    vsum[mt][rh] += __shfl_xor_sync(0xffffffffu, vsum[mt][rh], o);
        if (tq == 0)
            #pragma unroll
            for (int mt = 0; mt < 2; ++mt)
                #pragma unroll
                for (int rh = 0; rh < 2; ++rh)
                    sm->rp2[w][mt * 16 + rh * 8 + g] = vsum[mt][rh];
        __syncthreads();
        #pragma unroll
        for (int mt = 0; mt < 2; ++mt)
            #pragma unroll
            for (int rh = 0; rh < 2; ++rh) {
                const int row = mt * 16 + rh * 8 + g;
                rs[mt][rh] = rsqrtf((sm->rp2[0][row] + sm->rp2[1][row] +
                                     sm->rp2[2][row] + sm->rp2[3][row]) * (1.0f / 256.0f)
                                    + 1e-5f);
            }
    }

    // ---- LN2 apply + max over 32 rows per column. ----
    {
        #pragma unroll
        for (int nt = 0; nt < 8; ++nt) {
            const float2 gp = *(const float2*)&g2[ncol0 + nt * 8];
            const float2 ep = *(const float2*)&be2[ncol0 + nt * 8];
            float m0 = -3.402823466e38f, m1 = m0;
            #pragma unroll
            for (int mt = 0; mt < 2; ++mt)
                #pragma unroll
                for (int rh = 0; rh < 2; ++rh) {
                    m0 = fmaxf(m0, (acc[mt][nt][2 * rh]     - mu[mt][rh]) * rs[mt][rh] * gp.x + ep.x);
                    m1 = fmaxf(m1, (acc[mt][nt][2 * rh + 1] - mu[mt][rh]) * rs[mt][rh] * gp.y + ep.y);
                }
            #pragma unroll
            for (int o = 4; o <= 16; o <<= 1) {       // reduce over g (rows)
                m0 = fmaxf(m0, __shfl_xor_sync(0xffffffffu, m0, o));
                m1 = fmaxf(m1, __shfl_xor_sync(0xffffffffu, m1, o));
            }
            if (lane < 4) {
                out[(size_t)bs * PC + ncol0 + nt * 8]     = m0;
                out[(size_t)bs * PC + ncol0 + nt * 8 + 1] = m1;
            }
        }
    }
}

extern "C" void kernel_launch(void* const* d_in, const int* in_sizes, int n_in,
                              void* d_out, int out_size) {
    const float* xyz    = (const float*)d_in[0];
    const float* feat   = (const float*)d_in[1];
    const float* center = (const float*)d_in[2];
    const float* W1     = (const float*)d_in[3];
    const float* b1     = (const float*)d_in[4];
    const float* g1     = (const float*)d_in[5];
    const float* be1    = (const float*)d_in[6];
    const float* W2     = (const float*)d_in[7];
    const float* b2     = (const float*)d_in[8];
    const float* g2     = (const float*)d_in[9];
    const float* be2    = (const float*)d_in[10];
    float* out = (float*)d_out;

    prep_kernel<<<(6144 + 16384 + 255) / 256, 256>>>(W1, W2);

    cudaFuncSetAttribute(lpe_kernel, cudaFuncAttributeMaxDynamicSharedMemorySize,
                         (int)sizeof(Smem));
    lpe_kernel<<<NB * NS, 128, sizeof(Smem)>>>(xyz, feat, center, b1, g1, be1,
                                               b2, g2, be2, out);
}

// round 7
// speedup vs baseline: 3.0236x; 1.0012x over previous
#include <cuda_runtime.h>
#include <math.h>
#include <stdint.h>

#define NB 8
#define NPTS 16384
#define NS 1024
#define PC 256
#define R2 0.0625f

// ---- precomputed W fragments (B-operand layout for mma.m16n8k16) ----
// index = (kt*32 + nt)*32 + lane ; {x,y,z,w} = {b0hi, b1hi, b0lo, b1lo}
__device__ uint4 W1frag[6 * 32 * 32];     // K padded 91 -> 96
__device__ uint4 W2frag[16 * 32 * 32];

__device__ __forceinline__ unsigned pack_bf16(float e0, float e1) {
    unsigned r;
    asm("cvt.rn.bf16x2.f32 %0, %1, %2;" : "=r"(r) : "f"(e1), "f"(e0));
    return r;   // low half = bf16(e0), high half = bf16(e1)
}
__device__ __forceinline__ void split2(float e0, float e1, unsigned &hi, unsigned &lo) {
    hi = pack_bf16(e0, e1);
    const float h0 = __uint_as_float(hi << 16);
    const float h1 = __uint_as_float(hi & 0xffff0000u);
    lo = pack_bf16(e0 - h0, e1 - h1);
}
__device__ __forceinline__ void mma16816(float* c, unsigned a0, unsigned a1,
                                         unsigned a2, unsigned a3,
                                         unsigned b0, unsigned b1) {
    asm("mma.sync.aligned.m16n8k16.row.col.f32.bf16.bf16.f32 "
        "{%0,%1,%2,%3}, {%4,%5,%6,%7}, {%8,%9}, {%0,%1,%2,%3};"
        : "+f"(c[0]), "+f"(c[1]), "+f"(c[2]), "+f"(c[3])
        : "r"(a0), "r"(a1), "r"(a2), "r"(a3), "r"(b0), "r"(b1));
}

// ---- prep: build W fragments (runs every launch; idempotent) ----
__global__ void prep_kernel(const float* __restrict__ W1, const float* __restrict__ W2) {
    const int t = blockIdx.x * blockDim.x + threadIdx.x;
    if (t < 6144) {                                   // W1: 6 kt * 32 nt * 32 lanes
        const int lane = t & 31, nt = (t >> 5) & 31, kt = t >> 10;
        const int k0 = kt * 16 + (lane & 3) * 2;
        const int n  = nt * 8 + (lane >> 2);
        const float e00 = (k0     < 91) ? W1[(k0    ) * PC + n] : 0.f;
        const float e01 = (k0 + 1 < 91) ? W1[(k0 + 1) * PC + n] : 0.f;
        const float e10 = (k0 + 8 < 91) ? W1[(k0 + 8) * PC + n] : 0.f;
        const float e11 = (k0 + 9 < 91) ? W1[(k0 + 9) * PC + n] : 0.f;
        uint4 v;
        split2(e00, e01, v.x, v.z);
        split2(e10, e11, v.y, v.w);
        W1frag[t] = v;
    } else if (t < 6144 + 16384) {                    // W2: 16 kt * 32 nt * 32 lanes
        const int u = t - 6144;
        const int lane = u & 31, nt = (u >> 5) & 31, kt = u >> 10;
        const int k0 = kt * 16 + (lane & 3) * 2;
        const int n  = nt * 8 + (lane >> 2);
        uint4 v;
        split2(W2[k0 * PC + n],       W2[(k0 + 1) * PC + n], v.x, v.z);
        split2(W2[(k0 + 8) * PC + n], W2[(k0 + 9) * PC + n], v.y, v.w);
        W2frag[u] = v;
    }
}

struct Smem {
    float Xs[32][98];               // grouped input fp32 (K padded to 96, +2 stride pad)
    uint4 Hfrag[16][2][32][2];      // [kt][mt][lane][{hi,lo}] A-fragments of H, 32 KB
    float rp1[4][32];               // cross-warp row partials
    float rp2[4][32];
    int   sc_idx[4][32];
    int   sc_cnt[4];
    int   gidx[32];
};

__global__ __launch_bounds__(128, 3)
void lpe_kernel(const float* __restrict__ xyz, const float* __restrict__ feat,
                const float* __restrict__ center,
                const float* __restrict__ b1, const float* __restrict__ g1,
                const float* __restrict__ be1,
                const float* __restrict__ b2, const float* __restrict__ g2,
                const float* __restrict__ be2,
                float* __restrict__ out)
{
    extern __shared__ char rawsm[];
    Smem* sm = (Smem*)rawsm;

    const int bs   = blockIdx.x;
    const int b    = bs >> 10;
    const int tid  = threadIdx.x;
    const int w    = tid >> 5;
    const int lane = tid & 31;
    const int g    = lane >> 2;       // 0..7
    const int tq   = lane & 3;        // 0..3

    const float cx = center[bs * 3 + 0];
    const float cy = center[bs * 3 + 1];
    const float cz = center[bs * 3 + 2];
    const float cs = __fadd_rn(__fadd_rn(__fmul_rn(cx, cx), __fmul_rn(cy, cy)),
                               __fmul_rn(cz, cz));

    // ---- Phase 1: ball query, 4 warps x 4096-point segments, first-32 kept. ----
    {
        const float* xb = xyz + (size_t)b * NPTS * 3;
        int cnt = 0;
        const int base = w * 4096;
        for (int it = 0; it < 128; ++it) {
            const int n = base + it * 32 + lane;
            const float px = xb[n * 3 + 0];
            const float py = xb[n * 3 + 1];
            const float pz = xb[n * 3 + 2];
            const float ps = __fadd_rn(__fadd_rn(__fmul_rn(px, px), __fmul_rn(py, py)),
                                       __fmul_rn(pz, pz));
            const float dt = __fadd_rn(__fadd_rn(__fmul_rn(cx, px), __fmul_rn(cy, py)),
                                       __fmul_rn(cz, pz));
            const float sq = __fsub_rn(__fadd_rn(cs, ps), __fmul_rn(2.0f, dt));
            const bool hit = (sq <= R2);
            const unsigned m = __ballot_sync(0xffffffffu, hit);
            const int rank = __popc(m & ((1u << lane) - 1u));
            if (hit && (cnt + rank) < 32) sm->sc_idx[w][cnt + rank] = n;
            cnt += __popc(m);
            if (cnt >= 32) break;
        }
        if (lane == 0) sm->sc_cnt[w] = cnt < 32 ? cnt : 32;
    }
    __syncthreads();

    if (w == 0) {
        int val = NPTS, tot = 0;
        #pragma unroll
        for (int ww = 0; ww < 4; ++ww) {
            const int c = sm->sc_cnt[ww];
            if (lane >= tot && lane < tot + c) val = sm->sc_idx[ww][lane - tot];
            tot += c;
        }
        const int v0 = __shfl_sync(0xffffffffu, val, 0);
        if (val == NPTS) val = v0;
        sm->gidx[lane] = val < (NPTS - 1) ? val : (NPTS - 1);
        out[(size_t)NB * NS * PC + (size_t)bs * 32 + lane] = (float)val;
    }
    __syncthreads();

    // ---- Phase 2: gather + rel-pos into Xs (fp32, non-duplicated). ----
    if (tid < 96) {
        const int k = tid / 3, d = tid - k * 3;
        const int gi = sm->gidx[k];
        const float cd = (d == 0) ? cx : ((d == 1) ? cy : cz);
        sm->Xs[k][64 + d] = xyz[((size_t)b * NPTS + gi) * 3 + d] - cd;
    }
    #pragma unroll
    for (int t = tid; t < 512; t += 128) {
        const int k = t >> 4, c = (t & 15) * 4;
        const float4 v = *(const float4*)&feat[((size_t)b * NPTS + sm->gidx[k]) * 64 + c];
        sm->Xs[k][c + 0] = v.x; sm->Xs[k][c + 1] = v.y;
        sm->Xs[k][c + 2] = v.z; sm->Xs[k][c + 3] = v.w;
    }
    #pragma unroll
    for (int t = tid; t < 32 * 7; t += 128) {       // zero pad cols 91..97
        sm->Xs[t / 7][91 + t % 7] = 0.f;
    }
    __syncthreads();
    #pragma unroll
    for (int t = tid; t < 768; t += 128) {
        const int k = t / 24, c = t - k * 24;
        const int d = c >> 3, f = c & 7;
        const float r = sm->Xs[k][64 + d];
        const float a = r * (float)(1 << (f & 3));
        sm->Xs[k][67 + c] = (f < 4) ? sinf(a) : cosf(a);
    }
    __syncthreads();

    float acc[2][8][4];                 // [mt][nt][c0..c3]
    const int ncol0 = w * 64 + tq * 2;  // this lane's first col within warp cols

    // ---- GEMM1: C = X(32x96) @ W1(96x256), bf16 2-way split (3 MMAs). ----
    {
        #pragma unroll
        for (int nt = 0; nt < 8; ++nt) {
            const float2 bp = *(const float2*)&b1[ncol0 + nt * 8];
            acc[0][nt][0] = bp.x; acc[0][nt][1] = bp.y;
            acc[0][nt][2] = bp.x; acc[0][nt][3] = bp.y;
            acc[1][nt][0] = bp.x; acc[1][nt][1] = bp.y;
            acc[1][nt][2] = bp.x; acc[1][nt][3] = bp.y;
        }
        #pragma unroll
        for (int kt = 0; kt < 6; ++kt) {
            unsigned Ahi[2][4], Alo[2][4];
            #pragma unroll
            for (int mt = 0; mt < 2; ++mt) {
                const int r = mt * 16 + g;
                const int k0 = kt * 16 + tq * 2;
                const float2 p0 = *(const float2*)&sm->Xs[r][k0];
                const float2 p1 = *(const float2*)&sm->Xs[r + 8][k0];
                const float2 p2 = *(const float2*)&sm->Xs[r][k0 + 8];
                const float2 p3 = *(const float2*)&sm->Xs[r + 8][k0 + 8];
                split2(p0.x, p0.y, Ahi[mt][0], Alo[mt][0]);
                split2(p1.x, p1.y, Ahi[mt][1], Alo[mt][1]);
                split2(p2.x, p2.y, Ahi[mt][2], Alo[mt][2]);
                split2(p3.x, p3.y, Ahi[mt][3], Alo[mt][3]);
            }
            #pragma unroll
            for (int nt = 0; nt < 8; ++nt) {
                const uint4 B = W1frag[(kt * 32 + w * 8 + nt) * 32 + lane];
                #pragma unroll
                for (int mt = 0; mt < 2; ++mt) {
                    mma16816(acc[mt][nt], Ahi[mt][0], Ahi[mt][1], Ahi[mt][2], Ahi[mt][3], B.x, B.y);
                    mma16816(acc[mt][nt], Ahi[mt][0], Ahi[mt][1], Ahi[mt][2], Ahi[mt][3], B.z, B.w);
                    mma16816(acc[mt][nt], Alo[mt][0], Alo[mt][1], Alo[mt][2], Alo[mt][3], B.x, B.y);
                }
            }
        }
    }

    float mu[2][2], rs[2][2];

    // ---- LN1 stats: lane partials -> shfl over t -> cross-warp smem. ----
    {
        float s[2][2];
        #pragma unroll
        for (int mt = 0; mt < 2; ++mt)
            #pragma unroll
            for (int rh = 0; rh < 2; ++rh) {
                float v = 0.f;
                #pragma unroll
                for (int nt = 0; nt < 8; ++nt)
                    v += acc[mt][nt][2 * rh] + acc[mt][nt][2 * rh + 1];
                s[mt][rh] = v;
            }
        #pragma unroll
        for (int o = 1; o <= 2; o <<= 1)
            #pragma unroll
            for (int mt = 0; mt < 2; ++mt)
                #pragma unroll
                for (int rh = 0; rh < 2; ++rh)
                    s[mt][rh] += __shfl_xor_sync(0xffffffffu, s[mt][rh], o);
        if (tq == 0)
            #pragma unroll
            for (int mt = 0; mt < 2; ++mt)
                #pragma unroll
                for (int rh = 0; rh < 2; ++rh)
                    sm->rp1[w][mt * 16 + rh * 8 + g] = s[mt][rh];
        __syncthreads();
        #pragma unroll
        for (int mt = 0; mt < 2; ++mt)
            #pragma unroll
            for (int rh = 0; rh < 2; ++rh) {
                const int row = mt * 16 + rh * 8 + g;
                mu[mt][rh] = (sm->rp1[0][row] + sm->rp1[1][row] +
                              sm->rp1[2][row] + sm->rp1[3][row]) * (1.0f / 256.0f);
            }
        float vsum[2][2];
        #pragma unroll
        for (int mt = 0; mt < 2; ++mt)
            #pragma unroll
            for (int rh = 0; rh < 2; ++rh) {
                float v = 0.f;
                #pragma unroll
                for (int nt = 0; nt < 8; ++nt) {
                    const float d0 = acc[mt][nt][2 * rh]     - mu[mt][rh];
                    const float d1 = acc[mt][nt][2 * rh + 1] - mu[mt][rh];
                    v = fmaf(d0, d0, fmaf(d1, d1, v));
                }
                vsum[mt][rh] = v;
            }
        #pragma unroll
        for (int o = 1; o <= 2; o <<= 1)
            #pragma unroll
            for (int mt = 0; mt < 2; ++mt)
                #pragma unroll
                for (int rh = 0; rh < 2; ++rh)
                    vsum[mt][rh] += __shfl_xor_sync(0xffffffffu, vsum[mt][rh], o);
        if (tq == 0)
            #pragma unroll
            for (int mt = 0; mt < 2; ++mt)
                #pragma unroll
                for (int rh = 0; rh < 2; ++rh)
                    sm->rp2[w][mt * 16 + rh * 8 + g] = vsum[mt][rh];
        __syncthreads();
        #pragma unroll
        for (int mt = 0; mt < 2; ++mt)
            #pragma unroll
            for (int rh = 0; rh < 2; ++rh) {
                const int row = mt * 16 + rh * 8 + g;
                rs[mt][rh] = rsqrtf((sm->rp2[0][row] + sm->rp2[1][row] +
                                     sm->rp2[2][row] + sm->rp2[3][row]) * (1.0f / 256.0f)
                                    + 1e-5f);
            }
    }

    // ---- LN1 apply + GELU, pack into Hfrag (A-fragment layout for GEMM2). ----
    {
        #pragma unroll
        for (int mt = 0; mt < 2; ++mt)
            #pragma unroll
            for (int j = 0; j < 4; ++j) {
                float u[2][4];
                #pragma unroll
                for (int p = 0; p < 2; ++p) {          // ntiles 2j, 2j+1
                    const int nt = 2 * j + p;
                    const float2 gp = *(const float2*)&g1[ncol0 + nt * 8];
                    const float2 ep = *(const float2*)&be1[ncol0 + nt * 8];
                    #pragma unroll
                    for (int q = 0; q < 4; ++q) {
                        const int rh = q >> 1, e = q & 1;
                        const float gg = e ? gp.y : gp.x;
                        const float ee = e ? ep.y : ep.x;
                        const float t = (acc[mt][nt][q] - mu[mt][rh]) * rs[mt][rh] * gg + ee;
                        u[p][q] = 0.5f * t * (1.0f + erff(t * 0.70710678118654752440f));
                    }
                }
                uint4 hi, lo;
                split2(u[0][0], u[0][1], hi.x, lo.x);
                split2(u[0][2], u[0][3], hi.y, lo.y);
                split2(u[1][0], u[1][1], hi.z, lo.z);
                split2(u[1][2], u[1][3], hi.w, lo.w);
                sm->Hfrag[w * 4 + j][mt][lane][0] = hi;
                sm->Hfrag[w * 4 + j][mt][lane][1] = lo;
            }
    }
    __syncthreads();

    // ---- GEMM2: C = H(32x256) @ W2(256x256), bf16 2-way split. ----
    {
        #pragma unroll
        for (int nt = 0; nt < 8; ++nt) {
            const float2 bp = *(const float2*)&b2[ncol0 + nt * 8];
            acc[0][nt][0] = bp.x; acc[0][nt][1] = bp.y;
            acc[0][nt][2] = bp.x; acc[0][nt][3] = bp.y;
            acc[1][nt][0] = bp.x; acc[1][nt][1] = bp.y;
            acc[1][nt][2] = bp.x; acc[1][nt][3] = bp.y;
        }
        #pragma unroll 2
        for (int kt = 0; kt < 16; ++kt) {
            const uint4 Ahi0 = sm->Hfrag[kt][0][lane][0];
            const uint4 Alo0 = sm->Hfrag[kt][0][lane][1];
            const uint4 Ahi1 = sm->Hfrag[kt][1][lane][0];
            const uint4 Alo1 = sm->Hfrag[kt][1][lane][1];
            #pragma unroll
            for (int nt = 0; nt < 8; ++nt) {
                const uint4 B = W2frag[(kt * 32 + w * 8 + nt) * 32 + lane];
                mma16816(acc[0][nt], Ahi0.x, Ahi0.y, Ahi0.z, Ahi0.w, B.x, B.y);
                mma16816(acc[0][nt], Ahi0.x, Ahi0.y, Ahi0.z, Ahi0.w, B.z, B.w);
                mma16816(acc[0][nt], Alo0.x, Alo0.y, Alo0.z, Alo0.w, B.x, B.y);
                mma16816(acc[1][nt], Ahi1.x, Ahi1.y, Ahi1.z, Ahi1.w, B.x, B.y);
                mma16816(acc[1][nt], Ahi1.x, Ahi1.y, Ahi1.z, Ahi1.w, B.z, B.w);
                mma16816(acc[1][nt], Alo1.x, Alo1.y, Alo1.z, Alo1.w, B.x, B.y);
            }
        }
    }

    // ---- LN2 stats (same pattern). ----
    {
        float s[2][2];
        #pragma unroll
        for (int mt = 0; mt < 2; ++mt)
            #pragma unroll
            for (int rh = 0; rh < 2; ++rh) {
                float v = 0.f;
                #pragma unroll
                for (int nt = 0; nt < 8; ++nt)
                    v += acc[mt][nt][2 * rh] + acc[mt][nt][2 * rh + 1];
                s[mt][rh] = v;
            }
        #pragma unroll
        for (int o = 1; o <= 2; o <<= 1)
            #pragma unroll
            for (int mt = 0; mt < 2; ++mt)
                #pragma unroll
                for (int rh = 0; rh < 2; ++rh)
                    s[mt][rh] += __shfl_xor_sync(0xffffffffu, s[mt][rh], o);
        if (tq == 0)
            #pragma unroll
            for (int mt = 0; mt < 2; ++mt)
                #pragma unroll
                for (int rh = 0; rh < 2; ++rh)
                    sm->rp1[w][mt * 16 + rh * 8 + g] = s[mt][rh];
        __syncthreads();
        #pragma unroll
        for (int mt = 0; mt < 2; ++mt)
            #pragma unroll
            for (int rh = 0; rh < 2; ++rh) {
                const int row = mt * 16 + rh * 8 + g;
                mu[mt][rh] = (sm->rp1[0][row] + sm->rp1[1][row] +
                              sm->rp1[2][row] + sm->rp1[3][row]) * (1.0f / 256.0f);
            }
        float vsum[2][2];
        #pragma unroll
        for (int mt = 0; mt < 2; ++mt)
            #pragma unroll
            for (int rh = 0; rh < 2; ++rh) {
                float v = 0.f;
                #pragma unroll
                for (int nt = 0; nt < 8; ++nt) {
                    const float d0 = acc[mt][nt][2 * rh]     - mu[mt][rh];
                    const float d1 = acc[mt][nt][2 * rh + 1] - mu[mt][rh];
                    v = fmaf(d0, d0, fmaf(d1, d1, v));
                }
                vsum[mt][rh] = v;
            }
        #pragma unroll
        for (int o = 1; o <= 2; o <<= 1)
            #pragma unroll
            for (int mt = 0; mt < 2; ++mt)
                #pragma unroll
                for (int rh = 0; rh < 2; ++rh)
                    vsum[mt][rh] += __shfl_xor_sync(0xffffffffu, vsum[mt][rh], o);
        if (tq == 0)
            #pragma unroll
            for (int mt = 0; mt < 2; ++mt)
                #pragma unroll
                for (int rh = 0; rh < 2; ++rh)
                    sm->rp2[w][mt * 16 + rh * 8 + g] = vsum[mt][rh];
        __syncthreads();
        #pragma unroll
        for (int mt = 0; mt < 2; ++mt)
            #pragma unroll
            for (int rh = 0; rh < 2; ++rh) {
                const int row = mt * 16 + rh * 8 + g;
                rs[mt][rh] = rsqrtf((sm->rp2[0][row] + sm->rp2[1][row] +
                                     sm->rp2[2][row] + sm->rp2[3][row]) * (1.0f / 256.0f)
                                    + 1e-5f);
            }
    }

    // ---- LN2 apply + max over 32 rows per column. ----
    {
        #pragma unroll
        for (int nt = 0; nt < 8; ++nt) {
            const float2 gp = *(const float2*)&g2[ncol0 + nt * 8];
            const float2 ep = *(const float2*)&be2[ncol0 + nt * 8];
            float m0 = -3.402823466e38f, m1 = m0;
            #pragma unroll
            for (int mt = 0; mt < 2; ++mt)
                #pragma unroll
                for (int rh = 0; rh < 2; ++rh) {
                    m0 = fmaxf(m0, (acc[mt][nt][2 * rh]     - mu[mt][rh]) * rs[mt][rh] * gp.x + ep.x);
                    m1 = fmaxf(m1, (acc[mt][nt][2 * rh + 1] - mu[mt][rh]) * rs[mt][rh] * gp.y + ep.y);
                }
            #pragma unroll
            for (int o = 4; o <= 16; o <<= 1) {       // reduce over g (rows)
                m0 = fmaxf(m0, __shfl_xor_sync(0xffffffffu, m0, o));
                m1 = fmaxf(m1, __shfl_xor_sync(0xffffffffu, m1, o));
            }
            if (lane < 4) {
                out[(size_t)bs * PC + ncol0 + nt * 8]     = m0;
                out[(size_t)bs * PC + ncol0 + nt * 8 + 1] = m1;
            }
        }
    }
}

extern "C" void kernel_launch(void* const* d_in, const int* in_sizes, int n_in,
                              void* d_out, int out_size) {
    const float* xyz    = (const float*)d_in[0];
    const float* feat   = (const float*)d_in[1];
    const float* center = (const float*)d_in[2];
    const float* W1     = (const float*)d_in[3];
    const float* b1     = (const float*)d_in[4];
    const float* g1     = (const float*)d_in[5];
    const float* be1    = (const float*)d_in[6];
    const float* W2     = (const float*)d_in[7];
    const float* b2     = (const float*)d_in[8];
    const float* g2     = (const float*)d_in[9];
    const float* be2    = (const float*)d_in[10];
    float* out = (float*)d_out;

    prep_kernel<<<(6144 + 16384 + 255) / 256, 256>>>(W1, W2);

    cudaFuncSetAttribute(lpe_kernel, cudaFuncAttributeMaxDynamicSharedMemorySize,
                         (int)sizeof(Smem));
    lpe_kernel<<<NB * NS, 128, sizeof(Smem)>>>(xyz, feat, center, b1, g1, be1,
                                               b2, g2, be2, out);
}